// round 9
// baseline (speedup 1.0000x reference)
#include <cuda_runtime.h>
#include <math.h>

#define NMAX 50000
#define EMAX 400000
#define HASHSZ (1u<<20)
#define HASHMASK (HASHSZ-1u)
#define WSMEM (64*256*4)
#define PGRID 444

// ---------------- scratch ----------------
__device__ float g_X1 [NMAX*64];
__device__ float g_H  [NMAX*64];
__device__ float g_B1 [NMAX*64];
__device__ float g_B2 [NMAX*64];
__device__ float g_S  [NMAX*64];
__device__ unsigned long long g_GX[NMAX*128];
__device__ float g_dinv0[NMAX];
__device__ float g_dinvP[NMAX];
__device__ float g_score[NMAX];
__device__ float g_kept[NMAX];
__device__ float g_sdeg[NMAX];
__device__ unsigned g_key[NMAX];
__device__ int   g_icnt[NMAX];
__device__ int   g_cc[NMAX];
__device__ int   g_mi[NMAX];
__device__ int   g_pos[NMAX];
__device__ int   g_off[NMAX+1];
__device__ int   g_cur[NMAX];
__device__ int   g_eidx[EMAX];
__device__ int   g_hist[65536];
__device__ int   g_M;
__device__ float g_pwnorm;
__device__ unsigned long long g_hk[HASHSZ];
__device__ int   g_hc[HASHSZ];

__device__ __forceinline__ float sigf(float x){ return 1.0f/(1.0f+expf(-x)); }

#define FMA2(A,B,C) asm("fma.rn.f32x2 %0,%1,%2,%0;":"+l"(A):"l"(B),"l"(C))
#define PACK2(D,LO,HI) asm("mov.b64 %0,{%1,%2};":"=l"(D):"f"(LO),"f"(HI))
#define BCAST2(D,V) asm("mov.b64 %0,{%1,%1};":"=l"(D):"f"(V))
#define UNPACK2(LO,HI,S) asm("mov.b64 {%0,%1},%2;":"=f"(LO),"=f"(HI):"l"(S))

// ------- fused init ---------------------------------------------------------------
__global__ void k_init(const float* __restrict__ pw, int n){
    int i=blockIdx.x*blockDim.x+threadIdx.x;
    if(i<(int)HASHSZ){ g_hk[i]=~0ull; g_hc[i]=0; }
    if(i<n){ g_icnt[i]=0; g_cc[i]=0; }
    if(i<65536) g_hist[i]=0;
    if(blockIdx.x==0&&threadIdx.x<32){
        int l=threadIdx.x;
        float v=pw[l]*pw[l]+pw[l+32]*pw[l+32];
        for(int o=16;o;o>>=1) v+=__shfl_down_sync(0xffffffffu,v,o);
        if(l==0) g_pwnorm=sqrtf(v);
    }
}

// ------- edge pass: in-degree + hash insert ---------------------------------------
__device__ __forceinline__ unsigned hmix(unsigned long long x){
    x^=x>>30; x*=0xbf58476d1ce4e5b9ull;
    x^=x>>27; x*=0x94d049bb133111ebull;
    x^=x>>31;
    return (unsigned)x&HASHMASK;
}
__global__ void k_edge0(const int* __restrict__ row, const int* __restrict__ col, int e, int n){
    int i=blockIdx.x*blockDim.x+threadIdx.x;
    if(i>=e) return;
    atomicAdd(&g_icnt[col[i]],1);
    unsigned long long key=(unsigned long long)row[i]*(unsigned)n+(unsigned)col[i];
    unsigned h=hmix(key);
    while(true){
        unsigned long long prev=atomicCAS(&g_hk[h],~0ull,key);
        if(prev==~0ull||prev==key){ atomicAdd(&g_hc[h],1); break; }
        h=(h+1)&HASHMASK;
    }
}

// ------- single-block CSR scan ----------------------------------------------------
__global__ void k_scan_all(int n, int e){
    __shared__ int ps[1024];
    int t=threadIdx.x;
    int per=(n+1023)/1024;
    int start=t*per, end=start+per; if(end>n) end=n;
    int s=0;
    for(int i=start;i<end;i++){
        int v=g_icnt[i];
        g_dinv0[i]=rsqrtf((float)v+2.0f);
        s+=v;
    }
    ps[t]=s; __syncthreads();
    for(int o=1;o<1024;o<<=1){
        int u=(t>=o)?ps[t-o]:0; __syncthreads();
        ps[t]+=u; __syncthreads();
    }
    int base=ps[t]-s;
    for(int i=start;i<end;i++){
        g_off[i]=base; g_cur[i]=base;
        base+=g_icnt[i];
    }
    if(t==0) g_off[n]=e;
}
// ------- placement + ccK fused ----------------------------------------------------
__global__ void k_place(const int* __restrict__ row, const int* __restrict__ col, int e, int n){
    int i=blockIdx.x*blockDim.x+threadIdx.x;
    if(i>=e) return;
    int r=row[i], c=col[i];
    int p=atomicAdd(&g_cur[c],1);
    g_eidx[p]=r;
    unsigned long long key=(unsigned long long)c*(unsigned)n+(unsigned)r;
    unsigned h=hmix(key);
    int cnt=0;
    while(true){
        unsigned long long k2=g_hk[h];
        if(k2==key){ cnt=g_hc[h]; break; }
        if(k2==~0ull) break;
        h=(h+1)&HASHMASK;
    }
    if(cnt) atomicAdd(&g_cc[r],cnt);
}

// ------- dense GEMM (XIN=1: input row = (pos>=0?alt[pos]:X[row]) + add[row]) -------
template<int K,int XIN>
__global__ void k_gemm(const float* __restrict__ X, const float* __restrict__ W,
                       const float* __restrict__ rs, float* __restrict__ out,
                       const float* __restrict__ scale1,
                       float* __restrict__ out2, const float* __restrict__ scale2,
                       const float* __restrict__ alt, const float* __restrict__ add, int n){
    __shared__ float sW[K*64];
    __shared__ float sX[16*K];
    int tid=threadIdx.x;
    for(int i=tid;i<K*64;i+=256) sW[i]=W[i];
    int r0=blockIdx.x*16;
    for(int i=tid;i<16*K;i+=256){
        int rr=i/K, kk=i%K, row=r0+rr;
        float v=0.0f;
        if(row<n){
            if(XIN){
                int p=g_pos[row];
                v=((p>=0)?alt[p*64+kk]:X[row*64+kk])+add[row*64+kk];
            }else{
                v=X[row*K+kk]; if(rs) v*=rs[row];
            }
        }
        sX[i]=v;
    }
    __syncthreads();
    int c=tid&63, rg=tid>>6;
    float a0=0,a1=0,a2=0,a3=0;
    #pragma unroll 8
    for(int kk=0;kk<K;kk++){
        float w=sW[kk*64+c];
        a0+=sX[(rg*4+0)*K+kk]*w;
        a1+=sX[(rg*4+1)*K+kk]*w;
        a2+=sX[(rg*4+2)*K+kk]*w;
        a3+=sX[(rg*4+3)*K+kk]*w;
    }
    int row=r0+rg*4;
    #pragma unroll
    for(int rr=0;rr<4;rr++){
        float a=(rr==0)?a0:(rr==1)?a1:(rr==2)?a2:a3;
        if(row+rr<n){
            out[(row+rr)*64+c]=scale1?scale1[row+rr]*a:a;
            if(out2) out2[(row+rr)*64+c]=scale2[row+rr]*a;
        }
    }
}

// ------- paired-weight smem loader ------------------------------------------------
__device__ __forceinline__ void load_paired(float* sW, const float* __restrict__ W, int tid){
    for(int i=tid*4;i<256*64;i+=256*4){
        int g=i>>6, f0=i&63;
        int j=g>>5, lg=g&31, kp=j>>1, half=j&1;
        int dbase=kp*64+lg*2+half;
        float4 w=*(const float4*)&W[i];
        sW[dbase+(f0+0)*256]=w.x; sW[dbase+(f0+1)*256]=w.y;
        sW[dbase+(f0+2)*256]=w.z; sW[dbase+(f0+3)*256]=w.w;
    }
}

// ------- fused GCN gather + LSTM x-gate precompute --------------------------------
// MODE 1 (conv0): Hs unscaled, per-edge dinv0; relu + score + hist; out=X1
// MODE 0 (final): Hs pre-scaled by dinv0; plain; out=final xo
template<int MODE>
__global__ __launch_bounds__(256) void k_fing(const float* __restrict__ Hs,
    const float* __restrict__ b, const float* __restrict__ pw,
    const float* __restrict__ Wih, const float* __restrict__ bih,
    const float* __restrict__ bhh, float* __restrict__ out, int n){
    extern __shared__ float sWi[];
    int tid=threadIdx.x;
    load_paired(sWi,Wih,tid);
    __syncthreads();
    int wid=tid>>5, lane=tid&31;
    unsigned long long bs[4];
    #pragma unroll
    for(int kp=0;kp<4;kp++){
        float blo=bih[lane+64*kp]+bhh[lane+64*kp];
        float bhi=bih[lane+64*kp+32]+bhh[lane+64*kp+32];
        PACK2(bs[kp],blo,bhi);
    }
    float gblo=b[lane], gbhi=b[lane+32];
    float pwl=0.0f,pwh=0.0f;
    if(MODE==1){ pwl=pw[lane]; pwh=pw[lane+32]; }
    unsigned long long* G=g_GX;
    for(int node=blockIdx.x*8+wid; node<n; node+=gridDim.x*8){
        float d=g_dinv0[node];
        float alo,ahi;
        int s0=g_off[node], s1=g_off[node+1];
        if(MODE==1){
            alo=2.0f*d*Hs[node*64+lane]; ahi=2.0f*d*Hs[node*64+lane+32];
            for(int j=s0;j<s1;j++){
                int r=g_eidx[j];
                float dr=g_dinv0[r];
                alo+=dr*Hs[r*64+lane];
                ahi+=dr*Hs[r*64+lane+32];
            }
        }else{
            alo=2.0f*Hs[node*64+lane]; ahi=2.0f*Hs[node*64+lane+32];
            for(int j=s0;j<s1;j++){
                int r=g_eidx[j];
                alo+=Hs[r*64+lane];
                ahi+=Hs[r*64+lane+32];
            }
        }
        float vlo=d*alo+gblo, vhi=d*ahi+gbhi;
        if(MODE==1){ vlo=fmaxf(vlo,0.0f); vhi=fmaxf(vhi,0.0f); }
        out[node*64+lane]=vlo; out[node*64+lane+32]=vhi;
        if(MODE==1){
            float s=vlo*pwl+vhi*pwh;
            for(int o=16;o;o>>=1) s+=__shfl_down_sync(0xffffffffu,s,o);
            if(lane==0){
                float sc=tanhf(s/g_pwnorm);
                g_score[node]=sc;
                unsigned bb=__float_as_uint(sc);
                unsigned key=(bb&0x80000000u)?~bb:(bb|0x80000000u);
                g_key[node]=key;
                atomicAdd(&g_hist[key>>16],1);
            }
        }
        unsigned long long a0[4];
        #pragma unroll
        for(int kp=0;kp<4;kp++) a0[kp]=bs[kp];
        #define FG_F(F,XS) { \
            const unsigned long long* wp=(const unsigned long long*)&sWi[(F)*256]+lane; \
            unsigned long long w0=wp[0],w1=wp[32],w2=wp[64],w3=wp[96]; \
            float xv=__shfl_sync(0xffffffffu,XS,(F)&31); \
            unsigned long long p0; BCAST2(p0,xv); \
            FMA2(a0[0],p0,w0); FMA2(a0[1],p0,w1); FMA2(a0[2],p0,w2); FMA2(a0[3],p0,w3); }
        #pragma unroll 8
        for(int f=0;f<32;f++) FG_F(f,vlo)
        #pragma unroll 8
        for(int f=32;f<64;f++) FG_F(f,vhi)
        #undef FG_F
        #pragma unroll
        for(int kp=0;kp<4;kp++) G[node*128+kp*32+lane]=a0[kp];
    }
}

// ------- single-block selection: coarse16 + two 8-bit refinements + mark + mik ----
__global__ __launch_bounds__(1024) void k_select(const int* __restrict__ mask, int n, int kk){
    __shared__ int cs[256], fine[256], fh[256];
    __shared__ int stie[4096];
    __shared__ int sSelB, sB2, sRem, sRem2, sNeeded, sTcnt, sM;
    __shared__ unsigned sT;
    int t=threadIdx.x;
    // phase A: coarse (top-16 bins)
    if(t<256){
        int s=0;
        for(int b=0;b<256;b++) s+=g_hist[t*256+b];
        cs[t]=s;
    }
    __syncthreads();
    if(t==0){
        int acc=0, c;
        for(c=255;c>0;c--){ if(acc+cs[c]>=kk) break; acc+=cs[c]; }
        sSelB=c; sRem=acc;   // sRem temporarily holds "above groups" count
    }
    __syncthreads();
    if(t<256) fine[t]=g_hist[sSelB*256+t];
    __syncthreads();
    if(t==0){
        int acc=sRem, selB=0, before=0;
        for(int b=255;b>=0;b--){
            acc+=fine[b];
            if(acc>=kk){ selB=sSelB*256+b; before=acc-fine[b]; break; }
        }
        sSelB=selB; sRem=kk-before;
    }
    // phase B1: bits [8:16)
    if(t<256) fh[t]=0;
    __syncthreads();
    {
        int selB=sSelB;
        for(int i=t;i<n;i+=1024){
            unsigned u=g_key[i];
            if((int)(u>>16)==selB) atomicAdd(&fh[(u>>8)&0xFF],1);
        }
    }
    __syncthreads();
    if(t==0){
        int acc=0, b2=0, above=0;
        for(int b=255;b>=0;b--){
            acc+=fh[b];
            if(acc>=sRem){ b2=b; above=acc-fh[b]; break; }
        }
        sB2=b2; sRem2=sRem-above;
    }
    __syncthreads();
    if(t<256) fh[t]=0;
    __syncthreads();
    // phase B2: bits [0:8)
    {
        unsigned pre=((unsigned)sSelB<<8)|(unsigned)sB2;
        for(int i=t;i<n;i+=1024){
            unsigned u=g_key[i];
            if((u>>8)==pre) atomicAdd(&fh[u&0xFF],1);
        }
    }
    __syncthreads();
    if(t==0){
        int acc=0, b3=0, needed=0;
        for(int b=255;b>=0;b--){
            acc+=fh[b];
            if(acc>=sRem2){ b3=b; needed=sRem2-(acc-fh[b]); break; }
        }
        sT=((unsigned)sSelB<<16)|((unsigned)sB2<<8)|(unsigned)b3;
        sNeeded=needed; sTcnt=0; sM=0;
    }
    __syncthreads();
    // phase D: mark kept + ties + masked compaction
    {
        unsigned T=sT;
        for(int i=t;i<n;i+=1024){
            unsigned u=g_key[i];
            g_kept[i]=(u>T)?1.0f:0.0f;
            if(u==T){ int p=atomicAdd(&sTcnt,1); if(p<4096) stie[p]=i; }
            int p=-1;
            if(mask[i]!=0){ p=atomicAdd(&sM,1); g_mi[p]=i; }
            g_pos[i]=p;
        }
    }
    __syncthreads();
    // phase E: tie resolution (lowest indices first) + publish M
    if(t==0){
        int need=sNeeded, tc=sTcnt; if(tc>4096) tc=4096;
        for(int s=0;s<need&&s<tc;s++){
            int mb=s;
            for(int j=s+1;j<tc;j++) if(stie[j]<stie[mb]) mb=j;
            int tmp=stie[s]; stie[s]=stie[mb]; stie[mb]=tmp;
            g_kept[stie[s]]=1.0f;
        }
        g_M=sM;
    }
}

// ---------------- pooled degrees ----------------
__global__ void k_sdeg(int n){
    int i=blockIdx.x*blockDim.x+threadIdx.x;
    if(i>=n) return;
    float s=0.0f;
    for(int j=g_off[i];j<g_off[i+1];j++) s+=g_kept[g_eidx[j]];
    g_sdeg[i]=s;
}
__global__ void k_dinvPk(int n){
    int i=blockIdx.x*blockDim.x+threadIdx.x;
    if(i>=n) return;
    float td=0.0f;
    for(int j=g_off[i];j<g_off[i+1];j++) td+=g_sdeg[g_eidx[j]];
    float degP=td+2.0f*g_sdeg[i]+2.0f-(float)g_cc[i];
    g_dinvP[i]=(g_kept[i]>0.5f)?rsqrtf(degP):0.0f;
}
__global__ void k_sg(const float* __restrict__ m, float* __restrict__ s, int n){
    int node=(blockIdx.x*blockDim.x+threadIdx.x)>>5;
    int l=threadIdx.x&31;
    if(node>=n) return;
    float alo=0.0f, ahi=0.0f;
    int s0=g_off[node], s1=g_off[node+1];
    for(int j=s0;j<s1;j++){
        int r=g_eidx[j];
        alo+=m[r*64+l];
        ahi+=m[r*64+l+32];
    }
    s[node*64+l]=alo; s[node*64+l+32]=ahi;
}
__global__ void k_tup(const float* __restrict__ s, const float* __restrict__ h2,
                      const float* __restrict__ b1, float* __restrict__ up, int n){
    int node=(blockIdx.x*blockDim.x+threadIdx.x)>>5;
    int l=threadIdx.x&31;
    if(node>=n) return;
    float dp=g_dinvP[node];
    if(dp==0.0f){
        up[node*64+l]=0.0f; up[node*64+l+32]=0.0f;
        return;
    }
    float alo=0.0f, ahi=0.0f;
    int s0=g_off[node], s1=g_off[node+1];
    for(int j=s0;j<s1;j++){
        int r=g_eidx[j];
        alo+=s[r*64+l];
        ahi+=s[r*64+l+32];
    }
    float cf=(2.0f-(float)g_cc[node])*dp;
    float vlo=fmaxf(dp*(alo+2.0f*s[node*64+l]   +cf*h2[node*64+l])   +b1[l],   0.0f);
    float vhi=fmaxf(dp*(ahi+2.0f*s[node*64+l+32]+cf*h2[node*64+l+32])+b1[l+32],0.0f);
    up[node*64+l]=vlo; up[node*64+l+32]=vhi;
}

// ------- LSTM recurrence (h-part only). DIRECT=1 writes out[rid] rows -------------
template<int DIRECT>
__global__ __launch_bounds__(256) void k_lstm(
    const float* __restrict__ Whh, const float* __restrict__ bih,
    const float* __restrict__ bhh, float* __restrict__ out){
    extern __shared__ float sWh[];
    int tid=threadIdx.x;
    load_paired(sWh,Whh,tid);
    __syncthreads();
    int wid=tid>>5, lane=tid&31;
    int M=g_M;
    unsigned long long bs[4];
    #pragma unroll
    for(int kp=0;kp<4;kp++){
        float blo=bih[lane+64*kp]+bhh[lane+64*kp];
        float bhi=bih[lane+64*kp+32]+bhh[lane+64*kp+32];
        PACK2(bs[kp],blo,bhi);
    }
    const unsigned long long* G=g_GX;
    for(int base=(blockIdx.x*8+wid)*4; base<M; base+=gridDim.x*32){
        int rid[4];
        #pragma unroll
        for(int nn=0;nn<4;nn++) rid[nn]=(base+nn<M)?g_mi[base+nn]:-1;
        float hl[4]={0,0,0,0}, hh[4]={0,0,0,0}, cl[4]={0,0,0,0}, ch[4]={0,0,0,0};
        for(int t=0;t<5;t++){
            unsigned long long acc[4][4];
            #pragma unroll
            for(int nn=0;nn<4;nn++){
                int sr=rid[nn]-4+t;
                bool ok=(rid[nn]>=0)&&(sr>=0);
                const unsigned long long* gp=G+(ok?sr:0)*128+lane;
                #pragma unroll
                for(int kp=0;kp<4;kp++) acc[nn][kp]=ok?gp[kp*32]:bs[kp];
            }
            if(t>0){
                #define LSTM_F(F,HS) { \
                    const unsigned long long* whP=(const unsigned long long*)&sWh[(F)*256]+lane; \
                    unsigned long long w0=whP[0],w1=whP[32],w2=whP[64],w3=whP[96]; \
                    _Pragma("unroll") \
                    for(int nn=0;nn<4;nn++){ \
                        float hv=__shfl_sync(0xffffffffu,HS[nn],(F)&31); \
                        unsigned long long hp; BCAST2(hp,hv); \
                        FMA2(acc[nn][0],hp,w0); FMA2(acc[nn][1],hp,w1); \
                        FMA2(acc[nn][2],hp,w2); FMA2(acc[nn][3],hp,w3); \
                    } }
                #pragma unroll 8
                for(int f=0;f<32;f++) LSTM_F(f,hl)
                #pragma unroll 8
                for(int f=32;f<64;f++) LSTM_F(f,hh)
                #undef LSTM_F
            }
            #pragma unroll
            for(int nn=0;nn<4;nn++){
                float il,ih,fl,fh,gl,gh,ol,oh;
                UNPACK2(il,ih,acc[nn][0]);
                UNPACK2(fl,fh,acc[nn][1]);
                UNPACK2(gl,gh,acc[nn][2]);
                UNPACK2(ol,oh,acc[nn][3]);
                cl[nn]=sigf(fl)*cl[nn]+sigf(il)*tanhf(gl); hl[nn]=sigf(ol)*tanhf(cl[nn]);
                ch[nn]=sigf(fh)*ch[nn]+sigf(ih)*tanhf(gh); hh[nn]=sigf(oh)*tanhf(ch[nn]);
            }
        }
        #pragma unroll
        for(int nn=0;nn<4;nn++){
            if(rid[nn]>=0){
                int orow=DIRECT?rid[nn]:(base+nn);
                out[orow*64+lane]=hl[nn];
                out[orow*64+lane+32]=hh[nn];
            }
        }
    }
}

// ---------------- host ----------------
extern "C" void kernel_launch(void* const* d_in, const int* in_sizes, int n_in,
                              void* d_out, int out_size){
    const float* x=(const float*)d_in[0];
    const int* row=(const int*)d_in[1];
    const int* mask=(const int*)d_in[2];
    const float* W0=(const float*)d_in[3];  const float* b0=(const float*)d_in[4];
    const float* W1=(const float*)d_in[5];  const float* b1=(const float*)d_in[6];
    const float* pw=(const float*)d_in[7];
    const float* Wu=(const float*)d_in[8];  const float* bu=(const float*)d_in[9];
    const float* l0wih=(const float*)d_in[10]; const float* l0whh=(const float*)d_in[11];
    const float* l0bih=(const float*)d_in[12]; const float* l0bhh=(const float*)d_in[13];
    const float* fwih=(const float*)d_in[14];  const float* fwhh=(const float*)d_in[15];
    const float* fbih=(const float*)d_in[16];  const float* fbhh=(const float*)d_in[17];
    float* out=(float*)d_out;

    int n=in_sizes[0]/32;
    int e=in_sizes[1]/2;
    const int* col=row+e;
    int kk=(n+1)/2;
    int GN=(n+255)/256, GE=(e+255)/256;
    int GW=(n*32+255)/256;

    static cudaStream_t sA=0,sB=0;
    static cudaEvent_t evRoot=0,evG=0,evSel=0,evL0=0;
    if(!sA){
        cudaFuncSetAttribute(k_lstm<0>, cudaFuncAttributeMaxDynamicSharedMemorySize, WSMEM);
        cudaFuncSetAttribute(k_lstm<1>, cudaFuncAttributeMaxDynamicSharedMemorySize, WSMEM);
        cudaFuncSetAttribute(k_fing<0>, cudaFuncAttributeMaxDynamicSharedMemorySize, WSMEM);
        cudaFuncSetAttribute(k_fing<1>, cudaFuncAttributeMaxDynamicSharedMemorySize, WSMEM);
        cudaStreamCreateWithFlags(&sA,cudaStreamNonBlocking);
        cudaStreamCreateWithFlags(&sB,cudaStreamNonBlocking);
        cudaEventCreateWithFlags(&evRoot,cudaEventDisableTiming);
        cudaEventCreateWithFlags(&evG,cudaEventDisableTiming);
        cudaEventCreateWithFlags(&evSel,cudaEventDisableTiming);
        cudaEventCreateWithFlags(&evL0,cudaEventDisableTiming);
    }

    float *dX1,*dH,*dB1,*dB2,*dS;
    cudaGetSymbolAddress((void**)&dX1,g_X1);
    cudaGetSymbolAddress((void**)&dH,g_H);
    cudaGetSymbolAddress((void**)&dB1,g_B1);
    cudaGetSymbolAddress((void**)&dB2,g_B2);
    cudaGetSymbolAddress((void**)&dS,g_S);
    float *dscore; cudaGetSymbolAddress((void**)&dscore,g_score);
    float *ddinvP; cudaGetSymbolAddress((void**)&ddinvP,g_dinvP);
    float *ddinv0; cudaGetSymbolAddress((void**)&ddinv0,g_dinv0);

    // fork: conv0 GEMM on sA (depends on nothing)
    cudaEventRecord(evRoot,0);
    cudaStreamWaitEvent(sA,evRoot,0);
    k_gemm<32,0><<<(n+15)/16,256,0,sA>>>(x,W0,(const float*)0,dH,(const float*)0,(float*)0,(const float*)0,(const float*)0,(const float*)0,n);
    cudaEventRecord(evG,sA);

    // main: init + edges + CSR (+cc fused into place)
    k_init<<<(int)(HASHSZ/256),256>>>(pw,n);
    k_edge0<<<GE,256>>>(row,col,e,n);
    k_scan_all<<<1,1024>>>(n,e);
    k_place<<<GE,256>>>(row,col,e,n);

    // conv0 gather + score + LSTM0 x-gates, all fused
    cudaStreamWaitEvent(0,evG,0);
    k_fing<1><<<PGRID,256,WSMEM>>>(dH,b0,pw,l0wih,l0bih,l0bhh,dX1,n);

    // selection (single block)
    k_select<<<1,1024>>>(mask,n,kk);
    cudaEventRecord(evSel,0);

    // LSTM0 recurrence on sB
    cudaStreamWaitEvent(sB,evSel,0);
    k_lstm<0><<<PGRID,256,WSMEM,sB>>>(l0whh,l0bih,l0bhh,dB1);   // h0 -> B1 compact
    cudaEventRecord(evL0,sB);

    // branch A on main: pooled degrees + conv1
    k_sdeg<<<GN,256>>>(n);
    k_dinvPk<<<GN,256>>>(n);
    k_gemm<64,0><<<(n+15)/16,256>>>(dX1,W1,dscore,dH,(const float*)0,dB2,ddinvP,(const float*)0,(const float*)0,n); // h2->H, m->B2
    k_sg<<<GW,256>>>(dB2,dS,n);
    k_tup<<<GW,256>>>(dS,dH,b1,dB2,n);                          // up -> B2

    // join LSTM0; Wu GEMM with inline RES; final gather+gates; final LSTM
    cudaStreamWaitEvent(0,evL0,0);
    k_gemm<64,1><<<(n+15)/16,256>>>(dX1,Wu,(const float*)0,dH,ddinv0,(float*)0,(const float*)0,dB1,dB2,n);
    k_fing<0><<<PGRID,256,WSMEM>>>(dH,bu,(const float*)0,fwih,fbih,fbhh,out,n);
    k_lstm<1><<<PGRID,256,WSMEM>>>(fwhh,fbih,fbhh,out);
}

// round 10
// speedup vs baseline: 1.1337x; 1.1337x over previous
#include <cuda_runtime.h>
#include <math.h>

#define NMAX 50000
#define EMAX 400000
#define HASHSZ (1u<<20)
#define HASHMASK (HASHSZ-1u)
#define WSMEM (64*256*4)
#define PGRID 444

// ---------------- scratch ----------------
__device__ float g_X1 [NMAX*64];
__device__ float g_H  [NMAX*64];
__device__ float g_B1 [NMAX*64];
__device__ float g_B2 [NMAX*64];
__device__ float g_S  [NMAX*64];
__device__ unsigned long long g_GX[NMAX*128];
__device__ float g_dinv0[NMAX];
__device__ float g_dinvP[NMAX];
__device__ float g_score[NMAX];
__device__ float g_kept[NMAX];
__device__ float g_sdeg[NMAX];
__device__ unsigned g_key[NMAX];
__device__ int   g_icnt[NMAX];
__device__ int   g_cc[NMAX];
__device__ int   g_mi[NMAX];
__device__ int   g_pos[NMAX];
__device__ int   g_off[NMAX+1];
__device__ int   g_cur[NMAX];
__device__ int   g_eidx[EMAX];
__device__ int   g_bsum[256];
__device__ int   g_bscan[256];
__device__ int   g_hist[65536];
__device__ int   g_hist2[65536];
__device__ int   g_tie[4096];
__device__ int   g_M, g_tcnt, g_selB, g_before, g_needed;
__device__ unsigned g_T;
__device__ float g_pwnorm;
__device__ unsigned long long g_hk[HASHSZ];
__device__ int   g_hc[HASHSZ];

__device__ __forceinline__ float sigf(float x){ return 1.0f/(1.0f+expf(-x)); }

#define FMA2(A,B,C) asm("fma.rn.f32x2 %0,%1,%2,%0;":"+l"(A):"l"(B),"l"(C))
#define PACK2(D,LO,HI) asm("mov.b64 %0,{%1,%2};":"=l"(D):"f"(LO),"f"(HI))
#define BCAST2(D,V) asm("mov.b64 %0,{%1,%1};":"=l"(D):"f"(V))
#define UNPACK2(LO,HI,S) asm("mov.b64 {%0,%1},%2;":"=f"(LO),"=f"(HI):"l"(S))

// ------- fused init ---------------------------------------------------------------
__global__ void k_init(const float* __restrict__ pw, int n){
    int i=blockIdx.x*blockDim.x+threadIdx.x;
    if(i<(int)HASHSZ){ g_hk[i]=~0ull; g_hc[i]=0; }
    if(i<n){ g_icnt[i]=0; g_cc[i]=0; }
    if(i<65536){ g_hist[i]=0; g_hist2[i]=0; }
    if(i==0){ g_M=0; g_tcnt=0; }
    if(blockIdx.x==0&&threadIdx.x<32){
        int l=threadIdx.x;
        float v=pw[l]*pw[l]+pw[l+32]*pw[l+32];
        for(int o=16;o;o>>=1) v+=__shfl_down_sync(0xffffffffu,v,o);
        if(l==0) g_pwnorm=sqrtf(v);
    }
}

// ------- edge pass: in-degree + hash insert ---------------------------------------
__device__ __forceinline__ unsigned hmix(unsigned long long x){
    x^=x>>30; x*=0xbf58476d1ce4e5b9ull;
    x^=x>>27; x*=0x94d049bb133111ebull;
    x^=x>>31;
    return (unsigned)x&HASHMASK;
}
__global__ void k_edge0(const int* __restrict__ row, const int* __restrict__ col, int e, int n){
    int i=blockIdx.x*blockDim.x+threadIdx.x;
    if(i>=e) return;
    atomicAdd(&g_icnt[col[i]],1);
    unsigned long long key=(unsigned long long)row[i]*(unsigned)n+(unsigned)col[i];
    unsigned h=hmix(key);
    while(true){
        unsigned long long prev=atomicCAS(&g_hk[h],~0ull,key);
        if(prev==~0ull||prev==key){ atomicAdd(&g_hc[h],1); break; }
        h=(h+1)&HASHMASK;
    }
}

// ------- CSR build: multi-block 2-level scan --------------------------------------
__global__ void k_scan1(int n){
    __shared__ int s[256];
    int t=threadIdx.x, i=blockIdx.x*256+t;
    int v=(i<n)?g_icnt[i]:0;
    if(i<n) g_dinv0[i]=rsqrtf((float)v+2.0f);
    s[t]=v; __syncthreads();
    for(int o=128;o;o>>=1){ if(t<o) s[t]+=s[t+o]; __syncthreads(); }
    if(t==0) g_bsum[blockIdx.x]=s[0];
}
__global__ void k_scan2(int nb){
    __shared__ int s[256];
    int t=threadIdx.x;
    int v=(t<nb)?g_bsum[t]:0;
    s[t]=v; __syncthreads();
    for(int o=1;o<256;o<<=1){
        int u=(t>=o)?s[t-o]:0; __syncthreads();
        s[t]+=u; __syncthreads();
    }
    g_bscan[t]=s[t]-v;
}
__global__ void k_scan3(int n, int e){
    __shared__ int s[256];
    int t=threadIdx.x, i=blockIdx.x*256+t;
    int v=(i<n)?g_icnt[i]:0;
    s[t]=v; __syncthreads();
    for(int o=1;o<256;o<<=1){
        int u=(t>=o)?s[t-o]:0; __syncthreads();
        s[t]+=u; __syncthreads();
    }
    if(i<n){
        int off=g_bscan[blockIdx.x]+s[t]-v;
        g_off[i]=off; g_cur[i]=off;
        if(i==n-1) g_off[n]=e;
    }
}
// ------- placement + ccK fused ----------------------------------------------------
__global__ void k_place(const int* __restrict__ row, const int* __restrict__ col, int e, int n){
    int i=blockIdx.x*blockDim.x+threadIdx.x;
    if(i>=e) return;
    int r=row[i], c=col[i];
    int p=atomicAdd(&g_cur[c],1);
    g_eidx[p]=r;
    unsigned long long key=(unsigned long long)c*(unsigned)n+(unsigned)r;
    unsigned h=hmix(key);
    int cnt=0;
    while(true){
        unsigned long long k2=g_hk[h];
        if(k2==key){ cnt=g_hc[h]; break; }
        if(k2==~0ull) break;
        h=(h+1)&HASHMASK;
    }
    if(cnt) atomicAdd(&g_cc[r],cnt);
}

// ------- dense GEMM (XIN=1: input row = (pos>=0?alt[pos]:X[row]) + add[row]) -------
template<int K,int XIN>
__global__ void k_gemm(const float* __restrict__ X, const float* __restrict__ W,
                       const float* __restrict__ rs, float* __restrict__ out,
                       const float* __restrict__ scale1,
                       float* __restrict__ out2, const float* __restrict__ scale2,
                       const float* __restrict__ alt, const float* __restrict__ add, int n){
    __shared__ float sW[K*64];
    __shared__ float sX[16*K];
    int tid=threadIdx.x;
    for(int i=tid;i<K*64;i+=256) sW[i]=W[i];
    int r0=blockIdx.x*16;
    for(int i=tid;i<16*K;i+=256){
        int rr=i/K, kk=i%K, row=r0+rr;
        float v=0.0f;
        if(row<n){
            if(XIN){
                int p=g_pos[row];
                v=((p>=0)?alt[p*64+kk]:X[row*64+kk])+add[row*64+kk];
            }else{
                v=X[row*K+kk]; if(rs) v*=rs[row];
            }
        }
        sX[i]=v;
    }
    __syncthreads();
    int c=tid&63, rg=tid>>6;
    float a0=0,a1=0,a2=0,a3=0;
    #pragma unroll 8
    for(int kk=0;kk<K;kk++){
        float w=sW[kk*64+c];
        a0+=sX[(rg*4+0)*K+kk]*w;
        a1+=sX[(rg*4+1)*K+kk]*w;
        a2+=sX[(rg*4+2)*K+kk]*w;
        a3+=sX[(rg*4+3)*K+kk]*w;
    }
    int row=r0+rg*4;
    #pragma unroll
    for(int rr=0;rr<4;rr++){
        float a=(rr==0)?a0:(rr==1)?a1:(rr==2)?a2:a3;
        if(row+rr<n){
            out[(row+rr)*64+c]=scale1?scale1[row+rr]*a:a;
            if(out2) out2[(row+rr)*64+c]=scale2[row+rr]*a;
        }
    }
}

// ------- paired-weight smem loader ------------------------------------------------
__device__ __forceinline__ void load_paired(float* sW, const float* __restrict__ W, int tid){
    for(int i=tid*4;i<256*64;i+=256*4){
        int g=i>>6, f0=i&63;
        int j=g>>5, lg=g&31, kp=j>>1, half=j&1;
        int dbase=kp*64+lg*2+half;
        float4 w=*(const float4*)&W[i];
        sW[dbase+(f0+0)*256]=w.x; sW[dbase+(f0+1)*256]=w.y;
        sW[dbase+(f0+2)*256]=w.z; sW[dbase+(f0+3)*256]=w.w;
    }
}

// ------- fused GCN gather + LSTM x-gate precompute --------------------------------
// MODE 1 (conv0): Hs unscaled, per-edge dinv0; relu + score + hist; out=X1
// MODE 0 (final): Hs pre-scaled by dinv0; plain; out=final xo
template<int MODE>
__global__ __launch_bounds__(256) void k_fing(const float* __restrict__ Hs,
    const float* __restrict__ b, const float* __restrict__ pw,
    const float* __restrict__ Wih, const float* __restrict__ bih,
    const float* __restrict__ bhh, float* __restrict__ out, int n){
    extern __shared__ float sWi[];
    int tid=threadIdx.x;
    load_paired(sWi,Wih,tid);
    __syncthreads();
    int wid=tid>>5, lane=tid&31;
    unsigned long long bs[4];
    #pragma unroll
    for(int kp=0;kp<4;kp++){
        float blo=bih[lane+64*kp]+bhh[lane+64*kp];
        float bhi=bih[lane+64*kp+32]+bhh[lane+64*kp+32];
        PACK2(bs[kp],blo,bhi);
    }
    float gblo=b[lane], gbhi=b[lane+32];
    float pwl=0.0f,pwh=0.0f;
    if(MODE==1){ pwl=pw[lane]; pwh=pw[lane+32]; }
    unsigned long long* G=g_GX;
    for(int node=blockIdx.x*8+wid; node<n; node+=gridDim.x*8){
        float d=g_dinv0[node];
        float alo,ahi;
        int s0=g_off[node], s1=g_off[node+1];
        if(MODE==1){
            alo=2.0f*d*Hs[node*64+lane]; ahi=2.0f*d*Hs[node*64+lane+32];
            for(int j=s0;j<s1;j++){
                int r=g_eidx[j];
                float dr=g_dinv0[r];
                alo+=dr*Hs[r*64+lane];
                ahi+=dr*Hs[r*64+lane+32];
            }
        }else{
            alo=2.0f*Hs[node*64+lane]; ahi=2.0f*Hs[node*64+lane+32];
            for(int j=s0;j<s1;j++){
                int r=g_eidx[j];
                alo+=Hs[r*64+lane];
                ahi+=Hs[r*64+lane+32];
            }
        }
        float vlo=d*alo+gblo, vhi=d*ahi+gbhi;
        if(MODE==1){ vlo=fmaxf(vlo,0.0f); vhi=fmaxf(vhi,0.0f); }
        out[node*64+lane]=vlo; out[node*64+lane+32]=vhi;
        if(MODE==1){
            float s=vlo*pwl+vhi*pwh;
            for(int o=16;o;o>>=1) s+=__shfl_down_sync(0xffffffffu,s,o);
            if(lane==0){
                float sc=tanhf(s/g_pwnorm);
                g_score[node]=sc;
                unsigned bb=__float_as_uint(sc);
                unsigned key=(bb&0x80000000u)?~bb:(bb|0x80000000u);
                g_key[node]=key;
                atomicAdd(&g_hist[key>>16],1);
            }
        }
        unsigned long long a0[4];
        #pragma unroll
        for(int kp=0;kp<4;kp++) a0[kp]=bs[kp];
        #define FG_F(F,XS) { \
            const unsigned long long* wp=(const unsigned long long*)&sWi[(F)*256]+lane; \
            unsigned long long w0=wp[0],w1=wp[32],w2=wp[64],w3=wp[96]; \
            float xv=__shfl_sync(0xffffffffu,XS,(F)&31); \
            unsigned long long p0; BCAST2(p0,xv); \
            FMA2(a0[0],p0,w0); FMA2(a0[1],p0,w1); FMA2(a0[2],p0,w2); FMA2(a0[3],p0,w3); }
        #pragma unroll 8
        for(int f=0;f<32;f++) FG_F(f,vlo)
        #pragma unroll 8
        for(int f=32;f<64;f++) FG_F(f,vhi)
        #undef FG_F
        #pragma unroll
        for(int kp=0;kp<4;kp++) G[node*128+kp*32+lane]=a0[kp];
    }
}

// ---------------- radix select (multi-block, smem-staged serial scans) ------------
__global__ void k_find1(int kk){
    __shared__ int cs[256]; __shared__ int fine[256]; __shared__ int sel;
    int t=threadIdx.x, s=0;
    for(int b=0;b<256;b++) s+=g_hist[t*256+b];
    cs[t]=s; __syncthreads();
    if(t==0){
        int acc=0, c;
        for(c=255;c>0;c--){ if(acc+cs[c]>=kk) break; acc+=cs[c]; }
        sel=c; g_before=acc;
    }
    __syncthreads();
    int c=sel;
    fine[t]=g_hist[c*256+t];
    __syncthreads();
    if(t==0){
        int acc=g_before;
        for(int b=255;b>=0;b--){
            acc+=fine[b];
            if(acc>=kk){ g_selB=c*256+b; g_before=acc-fine[b]; return; }
        }
        g_selB=c*256;
    }
}
__global__ void k_hist2k(int n){
    int i=blockIdx.x*blockDim.x+threadIdx.x;
    if(i<n){ unsigned u=g_key[i]; if((int)(u>>16)==g_selB) atomicAdd(&g_hist2[u&0xFFFFu],1); }
}
__global__ void k_find2(int kk){
    __shared__ int cs[256]; __shared__ int fine[256]; __shared__ int sel;
    int t=threadIdx.x, s=0;
    for(int b=0;b<256;b++) s+=g_hist2[t*256+b];
    cs[t]=s; __syncthreads();
    int rem=kk-g_before;
    if(t==0){
        int acc=0, c;
        for(c=255;c>0;c--){ if(acc+cs[c]>=rem) break; acc+=cs[c]; }
        sel=c; g_needed=acc;
    }
    __syncthreads();
    int c=sel;
    fine[t]=g_hist2[c*256+t];
    __syncthreads();
    if(t==0){
        int acc=g_needed;
        for(int b=255;b>=0;b--){
            acc+=fine[b];
            if(acc>=rem){
                g_T=((unsigned)g_selB<<16)|(unsigned)(c*256+b);
                g_needed=rem-(acc-fine[b]);
                return;
            }
        }
        g_T=(unsigned)g_selB<<16; g_needed=0;
    }
}
__global__ void k_markmik(const int* __restrict__ mask, int n){
    int i=blockIdx.x*blockDim.x+threadIdx.x;
    if(i<n){
        unsigned u=g_key[i];
        g_kept[i]=(u>g_T)?1.0f:0.0f;
        if(u==g_T){ int p=atomicAdd(&g_tcnt,1); if(p<4096) g_tie[p]=i; }
        int p=-1;
        if(mask[i]!=0){ p=atomicAdd(&g_M,1); g_mi[p]=i; }
        g_pos[i]=p;
    }
}
__global__ void k_tiefix(){
    int need=g_needed, tc=g_tcnt; if(tc>4096) tc=4096;
    for(int s=0;s<need&&s<tc;s++){
        int mb=s;
        for(int j=s+1;j<tc;j++) if(g_tie[j]<g_tie[mb]) mb=j;
        int tmp=g_tie[s]; g_tie[s]=g_tie[mb]; g_tie[mb]=tmp;
        g_kept[g_tie[s]]=1.0f;
    }
}

// ---------------- pooled degrees ----------------
__global__ void k_sdeg(int n){
    int i=blockIdx.x*blockDim.x+threadIdx.x;
    if(i>=n) return;
    float s=0.0f;
    for(int j=g_off[i];j<g_off[i+1];j++) s+=g_kept[g_eidx[j]];
    g_sdeg[i]=s;
}
__global__ void k_dinvPk(int n){
    int i=blockIdx.x*blockDim.x+threadIdx.x;
    if(i>=n) return;
    float td=0.0f;
    for(int j=g_off[i];j<g_off[i+1];j++) td+=g_sdeg[g_eidx[j]];
    float degP=td+2.0f*g_sdeg[i]+2.0f-(float)g_cc[i];
    g_dinvP[i]=(g_kept[i]>0.5f)?rsqrtf(degP):0.0f;
}
__global__ void k_sg(const float* __restrict__ m, float* __restrict__ s, int n){
    int node=(blockIdx.x*blockDim.x+threadIdx.x)>>5;
    int l=threadIdx.x&31;
    if(node>=n) return;
    float alo=0.0f, ahi=0.0f;
    int s0=g_off[node], s1=g_off[node+1];
    for(int j=s0;j<s1;j++){
        int r=g_eidx[j];
        alo+=m[r*64+l];
        ahi+=m[r*64+l+32];
    }
    s[node*64+l]=alo; s[node*64+l+32]=ahi;
}
__global__ void k_tup(const float* __restrict__ s, const float* __restrict__ h2,
                      const float* __restrict__ b1, float* __restrict__ up, int n){
    int node=(blockIdx.x*blockDim.x+threadIdx.x)>>5;
    int l=threadIdx.x&31;
    if(node>=n) return;
    float dp=g_dinvP[node];
    if(dp==0.0f){
        up[node*64+l]=0.0f; up[node*64+l+32]=0.0f;
        return;
    }
    float alo=0.0f, ahi=0.0f;
    int s0=g_off[node], s1=g_off[node+1];
    for(int j=s0;j<s1;j++){
        int r=g_eidx[j];
        alo+=s[r*64+l];
        ahi+=s[r*64+l+32];
    }
    float cf=(2.0f-(float)g_cc[node])*dp;
    float vlo=fmaxf(dp*(alo+2.0f*s[node*64+l]   +cf*h2[node*64+l])   +b1[l],   0.0f);
    float vhi=fmaxf(dp*(ahi+2.0f*s[node*64+l+32]+cf*h2[node*64+l+32])+b1[l+32],0.0f);
    up[node*64+l]=vlo; up[node*64+l+32]=vhi;
}

// ------- LSTM recurrence (h-part only). DIRECT=1 writes out[rid] rows -------------
template<int DIRECT>
__global__ __launch_bounds__(256) void k_lstm(
    const float* __restrict__ Whh, const float* __restrict__ bih,
    const float* __restrict__ bhh, float* __restrict__ out){
    extern __shared__ float sWh[];
    int tid=threadIdx.x;
    load_paired(sWh,Whh,tid);
    __syncthreads();
    int wid=tid>>5, lane=tid&31;
    int M=g_M;
    unsigned long long bs[4];
    #pragma unroll
    for(int kp=0;kp<4;kp++){
        float blo=bih[lane+64*kp]+bhh[lane+64*kp];
        float bhi=bih[lane+64*kp+32]+bhh[lane+64*kp+32];
        PACK2(bs[kp],blo,bhi);
    }
    const unsigned long long* G=g_GX;
    for(int base=(blockIdx.x*8+wid)*4; base<M; base+=gridDim.x*32){
        int rid[4];
        #pragma unroll
        for(int nn=0;nn<4;nn++) rid[nn]=(base+nn<M)?g_mi[base+nn]:-1;
        float hl[4]={0,0,0,0}, hh[4]={0,0,0,0}, cl[4]={0,0,0,0}, ch[4]={0,0,0,0};
        for(int t=0;t<5;t++){
            unsigned long long acc[4][4];
            #pragma unroll
            for(int nn=0;nn<4;nn++){
                int sr=rid[nn]-4+t;
                bool ok=(rid[nn]>=0)&&(sr>=0);
                const unsigned long long* gp=G+(ok?sr:0)*128+lane;
                #pragma unroll
                for(int kp=0;kp<4;kp++) acc[nn][kp]=ok?gp[kp*32]:bs[kp];
            }
            if(t>0){
                #define LSTM_F(F,HS) { \
                    const unsigned long long* whP=(const unsigned long long*)&sWh[(F)*256]+lane; \
                    unsigned long long w0=whP[0],w1=whP[32],w2=whP[64],w3=whP[96]; \
                    _Pragma("unroll") \
                    for(int nn=0;nn<4;nn++){ \
                        float hv=__shfl_sync(0xffffffffu,HS[nn],(F)&31); \
                        unsigned long long hp; BCAST2(hp,hv); \
                        FMA2(acc[nn][0],hp,w0); FMA2(acc[nn][1],hp,w1); \
                        FMA2(acc[nn][2],hp,w2); FMA2(acc[nn][3],hp,w3); \
                    } }
                #pragma unroll 8
                for(int f=0;f<32;f++) LSTM_F(f,hl)
                #pragma unroll 8
                for(int f=32;f<64;f++) LSTM_F(f,hh)
                #undef LSTM_F
            }
            #pragma unroll
            for(int nn=0;nn<4;nn++){
                float il,ih,fl,fh,gl,gh,ol,oh;
                UNPACK2(il,ih,acc[nn][0]);
                UNPACK2(fl,fh,acc[nn][1]);
                UNPACK2(gl,gh,acc[nn][2]);
                UNPACK2(ol,oh,acc[nn][3]);
                cl[nn]=sigf(fl)*cl[nn]+sigf(il)*tanhf(gl); hl[nn]=sigf(ol)*tanhf(cl[nn]);
                ch[nn]=sigf(fh)*ch[nn]+sigf(ih)*tanhf(gh); hh[nn]=sigf(oh)*tanhf(ch[nn]);
            }
        }
        #pragma unroll
        for(int nn=0;nn<4;nn++){
            if(rid[nn]>=0){
                int orow=DIRECT?rid[nn]:(base+nn);
                out[orow*64+lane]=hl[nn];
                out[orow*64+lane+32]=hh[nn];
            }
        }
    }
}

// ---------------- host ----------------
extern "C" void kernel_launch(void* const* d_in, const int* in_sizes, int n_in,
                              void* d_out, int out_size){
    const float* x=(const float*)d_in[0];
    const int* row=(const int*)d_in[1];
    const int* mask=(const int*)d_in[2];
    const float* W0=(const float*)d_in[3];  const float* b0=(const float*)d_in[4];
    const float* W1=(const float*)d_in[5];  const float* b1=(const float*)d_in[6];
    const float* pw=(const float*)d_in[7];
    const float* Wu=(const float*)d_in[8];  const float* bu=(const float*)d_in[9];
    const float* l0wih=(const float*)d_in[10]; const float* l0whh=(const float*)d_in[11];
    const float* l0bih=(const float*)d_in[12]; const float* l0bhh=(const float*)d_in[13];
    const float* fwih=(const float*)d_in[14];  const float* fwhh=(const float*)d_in[15];
    const float* fbih=(const float*)d_in[16];  const float* fbhh=(const float*)d_in[17];
    float* out=(float*)d_out;

    int n=in_sizes[0]/32;
    int e=in_sizes[1]/2;
    const int* col=row+e;
    int kk=(n+1)/2;
    int GN=(n+255)/256, GE=(e+255)/256;
    int GW=(n*32+255)/256;

    static cudaStream_t sA=0,sB=0;
    static cudaEvent_t evRoot=0,evG=0,evSel=0,evL0=0;
    if(!sA){
        cudaFuncSetAttribute(k_lstm<0>, cudaFuncAttributeMaxDynamicSharedMemorySize, WSMEM);
        cudaFuncSetAttribute(k_lstm<1>, cudaFuncAttributeMaxDynamicSharedMemorySize, WSMEM);
        cudaFuncSetAttribute(k_fing<0>, cudaFuncAttributeMaxDynamicSharedMemorySize, WSMEM);
        cudaFuncSetAttribute(k_fing<1>, cudaFuncAttributeMaxDynamicSharedMemorySize, WSMEM);
        cudaStreamCreateWithFlags(&sA,cudaStreamNonBlocking);
        cudaStreamCreateWithFlags(&sB,cudaStreamNonBlocking);
        cudaEventCreateWithFlags(&evRoot,cudaEventDisableTiming);
        cudaEventCreateWithFlags(&evG,cudaEventDisableTiming);
        cudaEventCreateWithFlags(&evSel,cudaEventDisableTiming);
        cudaEventCreateWithFlags(&evL0,cudaEventDisableTiming);
    }

    float *dX1,*dH,*dB1,*dB2,*dS;
    cudaGetSymbolAddress((void**)&dX1,g_X1);
    cudaGetSymbolAddress((void**)&dH,g_H);
    cudaGetSymbolAddress((void**)&dB1,g_B1);
    cudaGetSymbolAddress((void**)&dB2,g_B2);
    cudaGetSymbolAddress((void**)&dS,g_S);
    float *dscore; cudaGetSymbolAddress((void**)&dscore,g_score);
    float *ddinvP; cudaGetSymbolAddress((void**)&ddinvP,g_dinvP);
    float *ddinv0; cudaGetSymbolAddress((void**)&ddinv0,g_dinv0);

    // fork: conv0 GEMM on sA (depends on nothing)
    cudaEventRecord(evRoot,0);
    cudaStreamWaitEvent(sA,evRoot,0);
    k_gemm<32,0><<<(n+15)/16,256,0,sA>>>(x,W0,(const float*)0,dH,(const float*)0,(float*)0,(const float*)0,(const float*)0,(const float*)0,n);
    cudaEventRecord(evG,sA);

    // main: init + edges + CSR (+cc fused into place)
    k_init<<<(int)(HASHSZ/256),256>>>(pw,n);
    k_edge0<<<GE,256>>>(row,col,e,n);
    k_scan1<<<GN,256>>>(n);
    k_scan2<<<1,256>>>(GN);
    k_scan3<<<GN,256>>>(n,e);
    k_place<<<GE,256>>>(row,col,e,n);

    // conv0 gather + score + LSTM0 x-gates, all fused
    cudaStreamWaitEvent(0,evG,0);
    k_fing<1><<<PGRID,256,WSMEM>>>(dH,b0,pw,l0wih,l0bih,l0bhh,dX1,n);

    // selection (multi-block chain)
    k_find1<<<1,256>>>(kk);
    k_hist2k<<<GN,256>>>(n);
    k_find2<<<1,256>>>(kk);
    k_markmik<<<GN,256>>>(mask,n);
    cudaEventRecord(evSel,0);
    k_tiefix<<<1,1>>>();

    // LSTM0 recurrence on sB
    cudaStreamWaitEvent(sB,evSel,0);
    k_lstm<0><<<PGRID,256,WSMEM,sB>>>(l0whh,l0bih,l0bhh,dB1);   // h0 -> B1 compact
    cudaEventRecord(evL0,sB);

    // branch A on main: pooled degrees + conv1
    k_sdeg<<<GN,256>>>(n);
    k_dinvPk<<<GN,256>>>(n);
    k_gemm<64,0><<<(n+15)/16,256>>>(dX1,W1,dscore,dH,(const float*)0,dB2,ddinvP,(const float*)0,(const float*)0,n); // h2->H, m->B2
    k_sg<<<GW,256>>>(dB2,dS,n);
    k_tup<<<GW,256>>>(dS,dH,b1,dB2,n);                          // up -> B2

    // join LSTM0; Wu GEMM with inline RES; final gather+gates; final LSTM
    cudaStreamWaitEvent(0,evL0,0);
    k_gemm<64,1><<<(n+15)/16,256>>>(dX1,Wu,(const float*)0,dH,ddinv0,(float*)0,(const float*)0,dB1,dB2,n);
    k_fing<0><<<PGRID,256,WSMEM>>>(dH,bu,(const float*)0,fwih,fbih,fbhh,out,n);
    k_lstm<1><<<PGRID,256,WSMEM>>>(fwhh,fbih,fbhh,out);
}

// round 11
// speedup vs baseline: 1.3911x; 1.2270x over previous
#include <cuda_runtime.h>
#include <math.h>

#define NMAX 50000
#define EMAX 400000
#define HASHSZ (1u<<20)
#define HASHMASK (HASHSZ-1u)
#define WSMEM (64*256*4)
#define PGRID 444

// ---------------- scratch ----------------
__device__ float g_X1 [NMAX*64];
__device__ float g_H  [NMAX*64];
__device__ float g_B1 [NMAX*64];
__device__ float g_B2 [NMAX*64];
__device__ float g_S  [NMAX*64];
__device__ unsigned long long g_GX[NMAX*128];
__device__ float g_dinv0[NMAX];
__device__ float g_dinvP[NMAX];
__device__ float g_score[NMAX];
__device__ float g_kept[NMAX];
__device__ float g_sdeg[NMAX];
__device__ unsigned g_key[NMAX];
__device__ int   g_icnt[NMAX];
__device__ int   g_cc[NMAX];
__device__ int   g_mi[NMAX];
__device__ int   g_pos[NMAX];
__device__ int   g_off[NMAX+1];
__device__ int   g_cur[NMAX];
__device__ int   g_eidx[EMAX];
__device__ int   g_bsum[256];
__device__ int   g_bscan[256];
__device__ int   g_hist[65536];
__device__ int   g_hist2[65536];
__device__ int   g_tie[4096];
__device__ int   g_M, g_tcnt, g_selB, g_before, g_needed;
__device__ unsigned g_T;
__device__ float g_pwnorm;
__device__ unsigned long long g_hk[HASHSZ];
__device__ int   g_hc[HASHSZ];

__device__ __forceinline__ float sigf(float x){ return 1.0f/(1.0f+expf(-x)); }

#define FMA2(A,B,C) asm("fma.rn.f32x2 %0,%1,%2,%0;":"+l"(A):"l"(B),"l"(C))
#define PACK2(D,LO,HI) asm("mov.b64 %0,{%1,%2};":"=l"(D):"f"(LO),"f"(HI))
#define BCAST2(D,V) asm("mov.b64 %0,{%1,%1};":"=l"(D):"f"(V))
#define UNPACK2(LO,HI,S) asm("mov.b64 {%0,%1},%2;":"=f"(LO),"=f"(HI):"l"(S))

// ------- fused init ---------------------------------------------------------------
__global__ void k_init(const float* __restrict__ pw, int n){
    int i=blockIdx.x*blockDim.x+threadIdx.x;
    if(i<(int)HASHSZ){ g_hk[i]=~0ull; g_hc[i]=0; }
    if(i<n){ g_icnt[i]=0; g_cc[i]=0; }
    if(i<65536){ g_hist[i]=0; g_hist2[i]=0; }
    if(i==0){ g_M=0; g_tcnt=0; }
    if(blockIdx.x==0&&threadIdx.x<32){
        int l=threadIdx.x;
        float v=pw[l]*pw[l]+pw[l+32]*pw[l+32];
        for(int o=16;o;o>>=1) v+=__shfl_down_sync(0xffffffffu,v,o);
        if(l==0) g_pwnorm=sqrtf(v);
    }
}

// ------- edge pass: in-degree + hash insert ---------------------------------------
__device__ __forceinline__ unsigned hmix(unsigned long long x){
    x^=x>>30; x*=0xbf58476d1ce4e5b9ull;
    x^=x>>27; x*=0x94d049bb133111ebull;
    x^=x>>31;
    return (unsigned)x&HASHMASK;
}
__global__ void k_edge0(const int* __restrict__ row, const int* __restrict__ col, int e, int n){
    int i=blockIdx.x*blockDim.x+threadIdx.x;
    if(i>=e) return;
    atomicAdd(&g_icnt[col[i]],1);
    unsigned long long key=(unsigned long long)row[i]*(unsigned)n+(unsigned)col[i];
    unsigned h=hmix(key);
    while(true){
        unsigned long long prev=atomicCAS(&g_hk[h],~0ull,key);
        if(prev==~0ull||prev==key){ atomicAdd(&g_hc[h],1); break; }
        h=(h+1)&HASHMASK;
    }
}

// ------- CSR build: multi-block 2-level scan --------------------------------------
__global__ void k_scan1(int n){
    __shared__ int s[256];
    int t=threadIdx.x, i=blockIdx.x*256+t;
    int v=(i<n)?g_icnt[i]:0;
    if(i<n) g_dinv0[i]=rsqrtf((float)v+2.0f);
    s[t]=v; __syncthreads();
    for(int o=128;o;o>>=1){ if(t<o) s[t]+=s[t+o]; __syncthreads(); }
    if(t==0) g_bsum[blockIdx.x]=s[0];
}
__global__ void k_scan2(int nb){
    __shared__ int s[256];
    int t=threadIdx.x;
    int v=(t<nb)?g_bsum[t]:0;
    s[t]=v; __syncthreads();
    for(int o=1;o<256;o<<=1){
        int u=(t>=o)?s[t-o]:0; __syncthreads();
        s[t]+=u; __syncthreads();
    }
    g_bscan[t]=s[t]-v;
}
__global__ void k_scan3(int n, int e){
    __shared__ int s[256];
    int t=threadIdx.x, i=blockIdx.x*256+t;
    int v=(i<n)?g_icnt[i]:0;
    s[t]=v; __syncthreads();
    for(int o=1;o<256;o<<=1){
        int u=(t>=o)?s[t-o]:0; __syncthreads();
        s[t]+=u; __syncthreads();
    }
    if(i<n){
        int off=g_bscan[blockIdx.x]+s[t]-v;
        g_off[i]=off; g_cur[i]=off;
        if(i==n-1) g_off[n]=e;
    }
}
// ------- placement + ccK fused ----------------------------------------------------
__global__ void k_place(const int* __restrict__ row, const int* __restrict__ col, int e, int n){
    int i=blockIdx.x*blockDim.x+threadIdx.x;
    if(i>=e) return;
    int r=row[i], c=col[i];
    int p=atomicAdd(&g_cur[c],1);
    g_eidx[p]=r;
    unsigned long long key=(unsigned long long)c*(unsigned)n+(unsigned)r;
    unsigned h=hmix(key);
    int cnt=0;
    while(true){
        unsigned long long k2=g_hk[h];
        if(k2==key){ cnt=g_hc[h]; break; }
        if(k2==~0ull) break;
        h=(h+1)&HASHMASK;
    }
    if(cnt) atomicAdd(&g_cc[r],cnt);
}

// ------- dense GEMM (XIN=1: input row = (pos>=0?alt[pos]:X[row]) + add[row]) -------
template<int K,int XIN>
__global__ void k_gemm(const float* __restrict__ X, const float* __restrict__ W,
                       const float* __restrict__ rs, float* __restrict__ out,
                       const float* __restrict__ scale1,
                       float* __restrict__ out2, const float* __restrict__ scale2,
                       const float* __restrict__ alt, const float* __restrict__ add, int n){
    __shared__ float sW[K*64];
    __shared__ float sX[16*K];
    int tid=threadIdx.x;
    for(int i=tid;i<K*64;i+=256) sW[i]=W[i];
    int r0=blockIdx.x*16;
    for(int i=tid;i<16*K;i+=256){
        int rr=i/K, kk=i%K, row=r0+rr;
        float v=0.0f;
        if(row<n){
            if(XIN){
                int p=g_pos[row];
                v=((p>=0)?alt[p*64+kk]:X[row*64+kk])+add[row*64+kk];
            }else{
                v=X[row*K+kk]; if(rs) v*=rs[row];
            }
        }
        sX[i]=v;
    }
    __syncthreads();
    int c=tid&63, rg=tid>>6;
    float a0=0,a1=0,a2=0,a3=0;
    #pragma unroll 8
    for(int kk=0;kk<K;kk++){
        float w=sW[kk*64+c];
        a0+=sX[(rg*4+0)*K+kk]*w;
        a1+=sX[(rg*4+1)*K+kk]*w;
        a2+=sX[(rg*4+2)*K+kk]*w;
        a3+=sX[(rg*4+3)*K+kk]*w;
    }
    int row=r0+rg*4;
    #pragma unroll
    for(int rr=0;rr<4;rr++){
        float a=(rr==0)?a0:(rr==1)?a1:(rr==2)?a2:a3;
        if(row+rr<n){
            out[(row+rr)*64+c]=scale1?scale1[row+rr]*a:a;
            if(out2) out2[(row+rr)*64+c]=scale2[row+rr]*a;
        }
    }
}

// ------- GCN gather (warp/node) ----------------------------------------------------
// MODE 1 (conv0): H unscaled; per-edge dinv0 scaling; relu + score + hist
// MODE 0 (final): H pre-scaled by dinv0; plain
template<int MODE>
__global__ void k_gcng(const float* __restrict__ Hs, const float* __restrict__ b,
                       const float* __restrict__ pw, float* __restrict__ out, int n){
    int node=(blockIdx.x*blockDim.x+threadIdx.x)>>5;
    int l=threadIdx.x&31;
    if(node>=n) return;
    float d=g_dinv0[node];
    float alo,ahi;
    int s0=g_off[node], s1=g_off[node+1];
    if(MODE==1){
        alo=2.0f*d*Hs[node*64+l]; ahi=2.0f*d*Hs[node*64+l+32];
        for(int j=s0;j<s1;j++){
            int r=g_eidx[j];
            float dr=g_dinv0[r];
            alo+=dr*Hs[r*64+l];
            ahi+=dr*Hs[r*64+l+32];
        }
    }else{
        alo=2.0f*Hs[node*64+l]; ahi=2.0f*Hs[node*64+l+32];
        for(int j=s0;j<s1;j++){
            int r=g_eidx[j];
            alo+=Hs[r*64+l];
            ahi+=Hs[r*64+l+32];
        }
    }
    float vlo=d*alo+b[l], vhi=d*ahi+b[l+32];
    if(MODE==1){
        vlo=fmaxf(vlo,0.0f); vhi=fmaxf(vhi,0.0f);
        out[node*64+l]=vlo; out[node*64+l+32]=vhi;
        float s=vlo*pw[l]+vhi*pw[l+32];
        for(int o=16;o;o>>=1) s+=__shfl_down_sync(0xffffffffu,s,o);
        if(l==0){
            float sc=tanhf(s/g_pwnorm);
            g_score[node]=sc;
            unsigned bb=__float_as_uint(sc);
            unsigned key=(bb&0x80000000u)?~bb:(bb|0x80000000u);
            g_key[node]=key;
            atomicAdd(&g_hist[key>>16],1);
        }
    }else{
        out[node*64+l]=vlo; out[node*64+l+32]=vhi;
    }
}
__global__ void k_sg(const float* __restrict__ m, float* __restrict__ s, int n){
    int node=(blockIdx.x*blockDim.x+threadIdx.x)>>5;
    int l=threadIdx.x&31;
    if(node>=n) return;
    float alo=0.0f, ahi=0.0f;
    int s0=g_off[node], s1=g_off[node+1];
    for(int j=s0;j<s1;j++){
        int r=g_eidx[j];
        alo+=m[r*64+l];
        ahi+=m[r*64+l+32];
    }
    s[node*64+l]=alo; s[node*64+l+32]=ahi;
}
__global__ void k_tup(const float* __restrict__ s, const float* __restrict__ h2,
                      const float* __restrict__ b1, float* __restrict__ up, int n){
    int node=(blockIdx.x*blockDim.x+threadIdx.x)>>5;
    int l=threadIdx.x&31;
    if(node>=n) return;
    float dp=g_dinvP[node];
    if(dp==0.0f){
        up[node*64+l]=0.0f; up[node*64+l+32]=0.0f;
        return;
    }
    float alo=0.0f, ahi=0.0f;
    int s0=g_off[node], s1=g_off[node+1];
    for(int j=s0;j<s1;j++){
        int r=g_eidx[j];
        alo+=s[r*64+l];
        ahi+=s[r*64+l+32];
    }
    float cf=(2.0f-(float)g_cc[node])*dp;
    float vlo=fmaxf(dp*(alo+2.0f*s[node*64+l]   +cf*h2[node*64+l])   +b1[l],   0.0f);
    float vhi=fmaxf(dp*(ahi+2.0f*s[node*64+l+32]+cf*h2[node*64+l+32])+b1[l+32],0.0f);
    up[node*64+l]=vlo; up[node*64+l+32]=vhi;
}

// ---------------- radix select (multi-block, smem-staged serial scans) ------------
__global__ void k_find1(int kk){
    __shared__ int cs[256]; __shared__ int fine[256]; __shared__ int sel;
    int t=threadIdx.x, s=0;
    for(int b=0;b<256;b++) s+=g_hist[t*256+b];
    cs[t]=s; __syncthreads();
    if(t==0){
        int acc=0, c;
        for(c=255;c>0;c--){ if(acc+cs[c]>=kk) break; acc+=cs[c]; }
        sel=c; g_before=acc;
    }
    __syncthreads();
    int c=sel;
    fine[t]=g_hist[c*256+t];
    __syncthreads();
    if(t==0){
        int acc=g_before;
        for(int b=255;b>=0;b--){
            acc+=fine[b];
            if(acc>=kk){ g_selB=c*256+b; g_before=acc-fine[b]; return; }
        }
        g_selB=c*256;
    }
}
__global__ void k_hist2k(int n){
    int i=blockIdx.x*blockDim.x+threadIdx.x;
    if(i<n){ unsigned u=g_key[i]; if((int)(u>>16)==g_selB) atomicAdd(&g_hist2[u&0xFFFFu],1); }
}
__global__ void k_find2(int kk){
    __shared__ int cs[256]; __shared__ int fine[256]; __shared__ int sel;
    int t=threadIdx.x, s=0;
    for(int b=0;b<256;b++) s+=g_hist2[t*256+b];
    cs[t]=s; __syncthreads();
    int rem=kk-g_before;
    if(t==0){
        int acc=0, c;
        for(c=255;c>0;c--){ if(acc+cs[c]>=rem) break; acc+=cs[c]; }
        sel=c; g_needed=acc;
    }
    __syncthreads();
    int c=sel;
    fine[t]=g_hist2[c*256+t];
    __syncthreads();
    if(t==0){
        int acc=g_needed;
        for(int b=255;b>=0;b--){
            acc+=fine[b];
            if(acc>=rem){
                g_T=((unsigned)g_selB<<16)|(unsigned)(c*256+b);
                g_needed=rem-(acc-fine[b]);
                return;
            }
        }
        g_T=(unsigned)g_selB<<16; g_needed=0;
    }
}
__global__ void k_markmik(const int* __restrict__ mask, int n){
    int i=blockIdx.x*blockDim.x+threadIdx.x;
    if(i<n){
        unsigned u=g_key[i];
        g_kept[i]=(u>g_T)?1.0f:0.0f;
        if(u==g_T){ int p=atomicAdd(&g_tcnt,1); if(p<4096) g_tie[p]=i; }
        int p=-1;
        if(mask[i]!=0){ p=atomicAdd(&g_M,1); g_mi[p]=i; }
        g_pos[i]=p;
    }
}
__global__ void k_tiefix(){
    int need=g_needed, tc=g_tcnt; if(tc>4096) tc=4096;
    for(int s=0;s<need&&s<tc;s++){
        int mb=s;
        for(int j=s+1;j<tc;j++) if(g_tie[j]<g_tie[mb]) mb=j;
        int tmp=g_tie[s]; g_tie[s]=g_tie[mb]; g_tie[mb]=tmp;
        g_kept[g_tie[s]]=1.0f;
    }
}

// ---------------- pooled degrees ----------------
__global__ void k_sdeg(int n){
    int i=blockIdx.x*blockDim.x+threadIdx.x;
    if(i>=n) return;
    float s=0.0f;
    for(int j=g_off[i];j<g_off[i+1];j++) s+=g_kept[g_eidx[j]];
    g_sdeg[i]=s;
}
__global__ void k_dinvPk(int n){
    int i=blockIdx.x*blockDim.x+threadIdx.x;
    if(i>=n) return;
    float td=0.0f;
    for(int j=g_off[i];j<g_off[i+1];j++) td+=g_sdeg[g_eidx[j]];
    float degP=td+2.0f*g_sdeg[i]+2.0f-(float)g_cc[i];
    g_dinvP[i]=(g_kept[i]>0.5f)?rsqrtf(degP):0.0f;
}

// ------- paired-weight smem loader ------------------------------------------------
__device__ __forceinline__ void load_paired(float* sW, const float* __restrict__ W, int tid){
    for(int i=tid*4;i<256*64;i+=256*4){
        int g=i>>6, f0=i&63;
        int j=g>>5, lg=g&31, kp=j>>1, half=j&1;
        int dbase=kp*64+lg*2+half;
        float4 w=*(const float4*)&W[i];
        sW[dbase+(f0+0)*256]=w.x; sW[dbase+(f0+1)*256]=w.y;
        sW[dbase+(f0+2)*256]=w.z; sW[dbase+(f0+3)*256]=w.w;
    }
}

// ------- Gx precompute ------------------------------------------------------------
__global__ __launch_bounds__(256) void k_gx(const float* __restrict__ Xsrc,
    const float* __restrict__ Wih, const float* __restrict__ bih,
    const float* __restrict__ bhh, int n){
    extern __shared__ float sWi[];
    int tid=threadIdx.x;
    load_paired(sWi,Wih,tid);
    __syncthreads();
    int wid=tid>>5, lane=tid&31;
    unsigned long long bs[4];
    #pragma unroll
    for(int kp=0;kp<4;kp++){
        float blo=bih[lane+64*kp]+bhh[lane+64*kp];
        float bhi=bih[lane+64*kp+32]+bhh[lane+64*kp+32];
        PACK2(bs[kp],blo,bhi);
    }
    unsigned long long* G=g_GX;
    for(int r0=(blockIdx.x*8+wid)*2; r0<n; r0+=gridDim.x*16){
        int r1=r0+1; bool has1=r1<n;
        float xl0=Xsrc[r0*64+lane], xh0=Xsrc[r0*64+lane+32];
        float xl1=has1?Xsrc[r1*64+lane]:0.0f, xh1=has1?Xsrc[r1*64+lane+32]:0.0f;
        unsigned long long a0[4],a1[4];
        #pragma unroll
        for(int kp=0;kp<4;kp++){ a0[kp]=bs[kp]; a1[kp]=bs[kp]; }
        #define GX_F(F,X0,X1S) { \
            const unsigned long long* wp=(const unsigned long long*)&sWi[(F)*256]+lane; \
            unsigned long long w0=wp[0],w1=wp[32],w2=wp[64],w3=wp[96]; \
            float xv0=__shfl_sync(0xffffffffu,X0,(F)&31); \
            float xv1=__shfl_sync(0xffffffffu,X1S,(F)&31); \
            unsigned long long p0,p1; BCAST2(p0,xv0); BCAST2(p1,xv1); \
            FMA2(a0[0],p0,w0); FMA2(a0[1],p0,w1); FMA2(a0[2],p0,w2); FMA2(a0[3],p0,w3); \
            FMA2(a1[0],p1,w0); FMA2(a1[1],p1,w1); FMA2(a1[2],p1,w2); FMA2(a1[3],p1,w3); }
        #pragma unroll 8
        for(int f=0;f<32;f++) GX_F(f,xl0,xl1)
        #pragma unroll 8
        for(int f=32;f<64;f++) GX_F(f,xh0,xh1)
        #undef GX_F
        #pragma unroll
        for(int kp=0;kp<4;kp++){
            G[r0*128+kp*32+lane]=a0[kp];
            if(has1) G[r1*128+kp*32+lane]=a1[kp];
        }
    }
}

// ------- LSTM recurrence (h-part only). DIRECT=1 writes out[rid] rows -------------
template<int DIRECT>
__global__ __launch_bounds__(256) void k_lstm(
    const float* __restrict__ Whh, const float* __restrict__ bih,
    const float* __restrict__ bhh, float* __restrict__ out){
    extern __shared__ float sWh[];
    int tid=threadIdx.x;
    load_paired(sWh,Whh,tid);
    __syncthreads();
    int wid=tid>>5, lane=tid&31;
    int M=g_M;
    unsigned long long bs[4];
    #pragma unroll
    for(int kp=0;kp<4;kp++){
        float blo=bih[lane+64*kp]+bhh[lane+64*kp];
        float bhi=bih[lane+64*kp+32]+bhh[lane+64*kp+32];
        PACK2(bs[kp],blo,bhi);
    }
    const unsigned long long* G=g_GX;
    for(int base=(blockIdx.x*8+wid)*4; base<M; base+=gridDim.x*32){
        int rid[4];
        #pragma unroll
        for(int nn=0;nn<4;nn++) rid[nn]=(base+nn<M)?g_mi[base+nn]:-1;
        float hl[4]={0,0,0,0}, hh[4]={0,0,0,0}, cl[4]={0,0,0,0}, ch[4]={0,0,0,0};
        for(int t=0;t<5;t++){
            unsigned long long acc[4][4];
            #pragma unroll
            for(int nn=0;nn<4;nn++){
                int sr=rid[nn]-4+t;
                bool ok=(rid[nn]>=0)&&(sr>=0);
                const unsigned long long* gp=G+(ok?sr:0)*128+lane;
                #pragma unroll
                for(int kp=0;kp<4;kp++) acc[nn][kp]=ok?gp[kp*32]:bs[kp];
            }
            if(t>0){
                #define LSTM_F(F,HS) { \
                    const unsigned long long* whP=(const unsigned long long*)&sWh[(F)*256]+lane; \
                    unsigned long long w0=whP[0],w1=whP[32],w2=whP[64],w3=whP[96]; \
                    _Pragma("unroll") \
                    for(int nn=0;nn<4;nn++){ \
                        float hv=__shfl_sync(0xffffffffu,HS[nn],(F)&31); \
                        unsigned long long hp; BCAST2(hp,hv); \
                        FMA2(acc[nn][0],hp,w0); FMA2(acc[nn][1],hp,w1); \
                        FMA2(acc[nn][2],hp,w2); FMA2(acc[nn][3],hp,w3); \
                    } }
                #pragma unroll 8
                for(int f=0;f<32;f++) LSTM_F(f,hl)
                #pragma unroll 8
                for(int f=32;f<64;f++) LSTM_F(f,hh)
                #undef LSTM_F
            }
            #pragma unroll
            for(int nn=0;nn<4;nn++){
                float il,ih,fl,fh,gl,gh,ol,oh;
                UNPACK2(il,ih,acc[nn][0]);
                UNPACK2(fl,fh,acc[nn][1]);
                UNPACK2(gl,gh,acc[nn][2]);
                UNPACK2(ol,oh,acc[nn][3]);
                cl[nn]=sigf(fl)*cl[nn]+sigf(il)*tanhf(gl); hl[nn]=sigf(ol)*tanhf(cl[nn]);
                ch[nn]=sigf(fh)*ch[nn]+sigf(ih)*tanhf(gh); hh[nn]=sigf(oh)*tanhf(ch[nn]);
            }
        }
        #pragma unroll
        for(int nn=0;nn<4;nn++){
            if(rid[nn]>=0){
                int orow=DIRECT?rid[nn]:(base+nn);
                out[orow*64+lane]=hl[nn];
                out[orow*64+lane+32]=hh[nn];
            }
        }
    }
}

// ---------------- host ----------------
extern "C" void kernel_launch(void* const* d_in, const int* in_sizes, int n_in,
                              void* d_out, int out_size){
    const float* x=(const float*)d_in[0];
    const int* row=(const int*)d_in[1];
    const int* mask=(const int*)d_in[2];
    const float* W0=(const float*)d_in[3];  const float* b0=(const float*)d_in[4];
    const float* W1=(const float*)d_in[5];  const float* b1=(const float*)d_in[6];
    const float* pw=(const float*)d_in[7];
    const float* Wu=(const float*)d_in[8];  const float* bu=(const float*)d_in[9];
    const float* l0wih=(const float*)d_in[10]; const float* l0whh=(const float*)d_in[11];
    const float* l0bih=(const float*)d_in[12]; const float* l0bhh=(const float*)d_in[13];
    const float* fwih=(const float*)d_in[14];  const float* fwhh=(const float*)d_in[15];
    const float* fbih=(const float*)d_in[16];  const float* fbhh=(const float*)d_in[17];
    float* out=(float*)d_out;

    int n=in_sizes[0]/32;
    int e=in_sizes[1]/2;
    const int* col=row+e;
    int kk=(n+1)/2;
    int GN=(n+255)/256, GE=(e+255)/256;
    int GW=(n*32+255)/256;

    static cudaStream_t sA=0,sB=0;
    static cudaEvent_t evRoot=0,evG=0,evX1=0,evMik=0,evL0=0;
    if(!sA){
        cudaFuncSetAttribute(k_lstm<0>, cudaFuncAttributeMaxDynamicSharedMemorySize, WSMEM);
        cudaFuncSetAttribute(k_lstm<1>, cudaFuncAttributeMaxDynamicSharedMemorySize, WSMEM);
        cudaFuncSetAttribute(k_gx,      cudaFuncAttributeMaxDynamicSharedMemorySize, WSMEM);
        cudaStreamCreateWithFlags(&sA,cudaStreamNonBlocking);
        cudaStreamCreateWithFlags(&sB,cudaStreamNonBlocking);
        cudaEventCreateWithFlags(&evRoot,cudaEventDisableTiming);
        cudaEventCreateWithFlags(&evG,cudaEventDisableTiming);
        cudaEventCreateWithFlags(&evX1,cudaEventDisableTiming);
        cudaEventCreateWithFlags(&evMik,cudaEventDisableTiming);
        cudaEventCreateWithFlags(&evL0,cudaEventDisableTiming);
    }

    float *dX1,*dH,*dB1,*dB2,*dS;
    cudaGetSymbolAddress((void**)&dX1,g_X1);
    cudaGetSymbolAddress((void**)&dH,g_H);
    cudaGetSymbolAddress((void**)&dB1,g_B1);
    cudaGetSymbolAddress((void**)&dB2,g_B2);
    cudaGetSymbolAddress((void**)&dS,g_S);
    float *dscore; cudaGetSymbolAddress((void**)&dscore,g_score);
    float *ddinvP; cudaGetSymbolAddress((void**)&ddinvP,g_dinvP);
    float *ddinv0; cudaGetSymbolAddress((void**)&ddinv0,g_dinv0);

    // fork: conv0 GEMM on sA (depends on nothing)
    cudaEventRecord(evRoot,0);
    cudaStreamWaitEvent(sA,evRoot,0);
    k_gemm<32,0><<<(n+15)/16,256,0,sA>>>(x,W0,(const float*)0,dH,(const float*)0,(float*)0,(const float*)0,(const float*)0,(const float*)0,n);
    cudaEventRecord(evG,sA);

    // main: init + edges + CSR (+cc fused into place)
    k_init<<<(int)(HASHSZ/256),256>>>(pw,n);
    k_edge0<<<GE,256>>>(row,col,e,n);
    k_scan1<<<GN,256>>>(n);
    k_scan2<<<1,256>>>(GN);
    k_scan3<<<GN,256>>>(n,e);
    k_place<<<GE,256>>>(row,col,e,n);

    // conv0 gather (needs H from sA + CSR)
    cudaStreamWaitEvent(0,evG,0);
    k_gcng<1><<<GW,256>>>(dH,b0,pw,dX1,n);
    cudaEventRecord(evX1,0);

    // LSTM0 Gx on sB (needs only X1)
    cudaStreamWaitEvent(sB,evX1,0);
    k_gx<<<PGRID,256,WSMEM,sB>>>(dX1,l0wih,l0bih,l0bhh,n);

    // selection on main
    k_find1<<<1,256>>>(kk);
    k_hist2k<<<GN,256>>>(n);
    k_find2<<<1,256>>>(kk);
    k_markmik<<<GN,256>>>(mask,n);
    cudaEventRecord(evMik,0);
    k_tiefix<<<1,1>>>();

    // LSTM0 recurrence on sB (needs g_mi/g_M)
    cudaStreamWaitEvent(sB,evMik,0);
    k_lstm<0><<<PGRID,256,WSMEM,sB>>>(l0whh,l0bih,l0bhh,dB1);   // h0 -> B1 compact
    cudaEventRecord(evL0,sB);

    // branch A on main: pooled degrees + conv1
    k_sdeg<<<GN,256>>>(n);
    k_dinvPk<<<GN,256>>>(n);
    k_gemm<64,0><<<(n+15)/16,256>>>(dX1,W1,dscore,dH,(const float*)0,dB2,ddinvP,(const float*)0,(const float*)0,n); // h2->H, m->B2
    k_sg<<<GW,256>>>(dB2,dS,n);
    k_tup<<<GW,256>>>(dS,dH,b1,dB2,n);                          // up -> B2

    // join LSTM0; Wu GEMM with inline RES; final gather; final LSTM
    cudaStreamWaitEvent(0,evL0,0);
    k_gemm<64,1><<<(n+15)/16,256>>>(dX1,Wu,(const float*)0,dH,ddinv0,(float*)0,(const float*)0,dB1,dB2,n);
    k_gcng<0><<<GW,256>>>(dH,bu,(const float*)0,out,n);
    k_gx<<<PGRID,256,WSMEM>>>(out,fwih,fbih,fbhh,n);
    k_lstm<1><<<PGRID,256,WSMEM>>>(fwhh,fbih,fbhh,out);
}

// round 12
// speedup vs baseline: 1.4313x; 1.0289x over previous
#include <cuda_runtime.h>
#include <math.h>

#define NMAX 50000
#define EMAX 400000
#define WSMEM (64*256*4)
#define PGRID 444

// ---------------- scratch ----------------
__device__ float g_X1 [NMAX*64];
__device__ float g_H  [NMAX*64];
__device__ float g_B1 [NMAX*64];
__device__ float g_B2 [NMAX*64];
__device__ float g_S  [NMAX*64];
__device__ unsigned long long g_GX[NMAX*128];
__device__ float g_dinv0[NMAX];
__device__ float g_dinvP[NMAX];
__device__ float g_score[NMAX];
__device__ float g_kept[NMAX];
__device__ float g_sdeg[NMAX];
__device__ unsigned g_key[NMAX];
__device__ int   g_icnt[NMAX];
__device__ int   g_cc[NMAX];
__device__ int   g_mi[NMAX];
__device__ int   g_pos[NMAX];
__device__ int   g_off[NMAX+1];
__device__ int   g_cur[NMAX];
__device__ int   g_eidx[EMAX];
__device__ int   g_bsum[256];
__device__ int   g_bscan[256];
__device__ int   g_hist[65536];
__device__ int   g_hist2[65536];
__device__ int   g_tie[4096];
__device__ int   g_M, g_tcnt, g_selB, g_before, g_needed;
__device__ unsigned g_T;
__device__ float g_pwnorm;

__device__ __forceinline__ float sigf(float x){ return 1.0f/(1.0f+expf(-x)); }

#define FMA2(A,B,C) asm("fma.rn.f32x2 %0,%1,%2,%0;":"+l"(A):"l"(B),"l"(C))
#define PACK2(D,LO,HI) asm("mov.b64 %0,{%1,%2};":"=l"(D):"f"(LO),"f"(HI))
#define BCAST2(D,V) asm("mov.b64 %0,{%1,%1};":"=l"(D):"f"(V))
#define UNPACK2(LO,HI,S) asm("mov.b64 {%0,%1},%2;":"=f"(LO),"=f"(HI):"l"(S))

// ------- fused init (no hash anymore — small clears only) --------------------------
__global__ void k_init(const float* __restrict__ pw, int n){
    int i=blockIdx.x*blockDim.x+threadIdx.x;
    if(i<n){ g_icnt[i]=0; g_cc[i]=0; }
    if(i<65536){ g_hist[i]=0; g_hist2[i]=0; }
    if(i==0){ g_M=0; g_tcnt=0; }
    if(blockIdx.x==0&&threadIdx.x<32){
        int l=threadIdx.x;
        float v=pw[l]*pw[l]+pw[l+32]*pw[l+32];
        for(int o=16;o;o>>=1) v+=__shfl_down_sync(0xffffffffu,v,o);
        if(l==0) g_pwnorm=sqrtf(v);
    }
}

// ------- edge pass: in-degree only -------------------------------------------------
__global__ void k_indeg(const int* __restrict__ col, int e){
    int i=blockIdx.x*blockDim.x+threadIdx.x;
    if(i<e) atomicAdd(&g_icnt[col[i]],1);
}

// ------- CSR build: multi-block 2-level scan --------------------------------------
__global__ void k_scan1(int n){
    __shared__ int s[256];
    int t=threadIdx.x, i=blockIdx.x*256+t;
    int v=(i<n)?g_icnt[i]:0;
    if(i<n) g_dinv0[i]=rsqrtf((float)v+2.0f);
    s[t]=v; __syncthreads();
    for(int o=128;o;o>>=1){ if(t<o) s[t]+=s[t+o]; __syncthreads(); }
    if(t==0) g_bsum[blockIdx.x]=s[0];
}
__global__ void k_scan2(int nb){
    __shared__ int s[256];
    int t=threadIdx.x;
    int v=(t<nb)?g_bsum[t]:0;
    s[t]=v; __syncthreads();
    for(int o=1;o<256;o<<=1){
        int u=(t>=o)?s[t-o]:0; __syncthreads();
        s[t]+=u; __syncthreads();
    }
    g_bscan[t]=s[t]-v;
}
__global__ void k_scan3(int n, int e){
    __shared__ int s[256];
    int t=threadIdx.x, i=blockIdx.x*256+t;
    int v=(i<n)?g_icnt[i]:0;
    s[t]=v; __syncthreads();
    for(int o=1;o<256;o<<=1){
        int u=(t>=o)?s[t-o]:0; __syncthreads();
        s[t]+=u; __syncthreads();
    }
    if(i<n){
        int off=g_bscan[blockIdx.x]+s[t]-v;
        g_off[i]=off; g_cur[i]=off;
        if(i==n-1) g_off[n]=e;
    }
}
// ------- placement (no hash) -------------------------------------------------------
__global__ void k_place(const int* __restrict__ row, const int* __restrict__ col, int e){
    int i=blockIdx.x*blockDim.x+threadIdx.x;
    if(i<e){
        int p=atomicAdd(&g_cur[col[i]],1);
        g_eidx[p]=row[i];
    }
}
// ------- cc via CSR count: cc[r] += #(c in eidx[off[r]..off[r+1])) per edge (r,c) --
__global__ void k_cc(const int* __restrict__ row, const int* __restrict__ col, int e){
    int i=blockIdx.x*blockDim.x+threadIdx.x;
    if(i>=e) return;
    int r=row[i], c=col[i];
    int s0=g_off[r], s1=g_off[r+1];
    int cnt=0;
    for(int j=s0;j<s1;j++) cnt+=(g_eidx[j]==c);
    if(cnt) atomicAdd(&g_cc[r],cnt);
}

// ------- dense GEMM (XIN=1: input row = (pos>=0?alt[pos]:X[row]) + add[row]) -------
template<int K,int XIN>
__global__ void k_gemm(const float* __restrict__ X, const float* __restrict__ W,
                       const float* __restrict__ rs, float* __restrict__ out,
                       const float* __restrict__ scale1,
                       float* __restrict__ out2, const float* __restrict__ scale2,
                       const float* __restrict__ alt, const float* __restrict__ add, int n){
    __shared__ float sW[K*64];
    __shared__ float sX[16*K];
    int tid=threadIdx.x;
    for(int i=tid;i<K*64;i+=256) sW[i]=W[i];
    int r0=blockIdx.x*16;
    for(int i=tid;i<16*K;i+=256){
        int rr=i/K, kk=i%K, row=r0+rr;
        float v=0.0f;
        if(row<n){
            if(XIN){
                int p=g_pos[row];
                v=((p>=0)?alt[p*64+kk]:X[row*64+kk])+add[row*64+kk];
            }else{
                v=X[row*K+kk]; if(rs) v*=rs[row];
            }
        }
        sX[i]=v;
    }
    __syncthreads();
    int c=tid&63, rg=tid>>6;
    float a0=0,a1=0,a2=0,a3=0;
    #pragma unroll 8
    for(int kk=0;kk<K;kk++){
        float w=sW[kk*64+c];
        a0+=sX[(rg*4+0)*K+kk]*w;
        a1+=sX[(rg*4+1)*K+kk]*w;
        a2+=sX[(rg*4+2)*K+kk]*w;
        a3+=sX[(rg*4+3)*K+kk]*w;
    }
    int row=r0+rg*4;
    #pragma unroll
    for(int rr=0;rr<4;rr++){
        float a=(rr==0)?a0:(rr==1)?a1:(rr==2)?a2:a3;
        if(row+rr<n){
            out[(row+rr)*64+c]=scale1?scale1[row+rr]*a:a;
            if(out2) out2[(row+rr)*64+c]=scale2[row+rr]*a;
        }
    }
}

// ------- GCN gather (warp/node) ----------------------------------------------------
template<int MODE>
__global__ void k_gcng(const float* __restrict__ Hs, const float* __restrict__ b,
                       const float* __restrict__ pw, float* __restrict__ out, int n){
    int node=(blockIdx.x*blockDim.x+threadIdx.x)>>5;
    int l=threadIdx.x&31;
    if(node>=n) return;
    float d=g_dinv0[node];
    float alo,ahi;
    int s0=g_off[node], s1=g_off[node+1];
    if(MODE==1){
        alo=2.0f*d*Hs[node*64+l]; ahi=2.0f*d*Hs[node*64+l+32];
        for(int j=s0;j<s1;j++){
            int r=g_eidx[j];
            float dr=g_dinv0[r];
            alo+=dr*Hs[r*64+l];
            ahi+=dr*Hs[r*64+l+32];
        }
    }else{
        alo=2.0f*Hs[node*64+l]; ahi=2.0f*Hs[node*64+l+32];
        for(int j=s0;j<s1;j++){
            int r=g_eidx[j];
            alo+=Hs[r*64+l];
            ahi+=Hs[r*64+l+32];
        }
    }
    float vlo=d*alo+b[l], vhi=d*ahi+b[l+32];
    if(MODE==1){
        vlo=fmaxf(vlo,0.0f); vhi=fmaxf(vhi,0.0f);
        out[node*64+l]=vlo; out[node*64+l+32]=vhi;
        float s=vlo*pw[l]+vhi*pw[l+32];
        for(int o=16;o;o>>=1) s+=__shfl_down_sync(0xffffffffu,s,o);
        if(l==0){
            float sc=tanhf(s/g_pwnorm);
            g_score[node]=sc;
            unsigned bb=__float_as_uint(sc);
            unsigned key=(bb&0x80000000u)?~bb:(bb|0x80000000u);
            g_key[node]=key;
            atomicAdd(&g_hist[key>>16],1);
        }
    }else{
        out[node*64+l]=vlo; out[node*64+l+32]=vhi;
    }
}
__global__ void k_sg(const float* __restrict__ m, float* __restrict__ s, int n){
    int node=(blockIdx.x*blockDim.x+threadIdx.x)>>5;
    int l=threadIdx.x&31;
    if(node>=n) return;
    float alo=0.0f, ahi=0.0f;
    int s0=g_off[node], s1=g_off[node+1];
    for(int j=s0;j<s1;j++){
        int r=g_eidx[j];
        alo+=m[r*64+l];
        ahi+=m[r*64+l+32];
    }
    s[node*64+l]=alo; s[node*64+l+32]=ahi;
}
__global__ void k_tup(const float* __restrict__ s, const float* __restrict__ h2,
                      const float* __restrict__ b1, float* __restrict__ up, int n){
    int node=(blockIdx.x*blockDim.x+threadIdx.x)>>5;
    int l=threadIdx.x&31;
    if(node>=n) return;
    float dp=g_dinvP[node];
    if(dp==0.0f){
        up[node*64+l]=0.0f; up[node*64+l+32]=0.0f;
        return;
    }
    float alo=0.0f, ahi=0.0f;
    int s0=g_off[node], s1=g_off[node+1];
    for(int j=s0;j<s1;j++){
        int r=g_eidx[j];
        alo+=s[r*64+l];
        ahi+=s[r*64+l+32];
    }
    float cf=(2.0f-(float)g_cc[node])*dp;
    float vlo=fmaxf(dp*(alo+2.0f*s[node*64+l]   +cf*h2[node*64+l])   +b1[l],   0.0f);
    float vhi=fmaxf(dp*(ahi+2.0f*s[node*64+l+32]+cf*h2[node*64+l+32])+b1[l+32],0.0f);
    up[node*64+l]=vlo; up[node*64+l+32]=vhi;
}

// ---------------- radix select ----------------
__global__ void k_find1(int kk){
    __shared__ int cs[256]; __shared__ int fine[256]; __shared__ int sel;
    int t=threadIdx.x, s=0;
    for(int b=0;b<256;b++) s+=g_hist[t*256+b];
    cs[t]=s; __syncthreads();
    if(t==0){
        int acc=0, c;
        for(c=255;c>0;c--){ if(acc+cs[c]>=kk) break; acc+=cs[c]; }
        sel=c; g_before=acc;
    }
    __syncthreads();
    int c=sel;
    fine[t]=g_hist[c*256+t];
    __syncthreads();
    if(t==0){
        int acc=g_before;
        for(int b=255;b>=0;b--){
            acc+=fine[b];
            if(acc>=kk){ g_selB=c*256+b; g_before=acc-fine[b]; return; }
        }
        g_selB=c*256;
    }
}
__global__ void k_hist2k(int n){
    int i=blockIdx.x*blockDim.x+threadIdx.x;
    if(i<n){ unsigned u=g_key[i]; if((int)(u>>16)==g_selB) atomicAdd(&g_hist2[u&0xFFFFu],1); }
}
__global__ void k_find2(int kk){
    __shared__ int cs[256]; __shared__ int fine[256]; __shared__ int sel;
    int t=threadIdx.x, s=0;
    for(int b=0;b<256;b++) s+=g_hist2[t*256+b];
    cs[t]=s; __syncthreads();
    int rem=kk-g_before;
    if(t==0){
        int acc=0, c;
        for(c=255;c>0;c--){ if(acc+cs[c]>=rem) break; acc+=cs[c]; }
        sel=c; g_needed=acc;
    }
    __syncthreads();
    int c=sel;
    fine[t]=g_hist2[c*256+t];
    __syncthreads();
    if(t==0){
        int acc=g_needed;
        for(int b=255;b>=0;b--){
            acc+=fine[b];
            if(acc>=rem){
                g_T=((unsigned)g_selB<<16)|(unsigned)(c*256+b);
                g_needed=rem-(acc-fine[b]);
                return;
            }
        }
        g_T=(unsigned)g_selB<<16; g_needed=0;
    }
}
__global__ void k_markmik(const int* __restrict__ mask, int n){
    int i=blockIdx.x*blockDim.x+threadIdx.x;
    if(i<n){
        unsigned u=g_key[i];
        g_kept[i]=(u>g_T)?1.0f:0.0f;
        if(u==g_T){ int p=atomicAdd(&g_tcnt,1); if(p<4096) g_tie[p]=i; }
        int p=-1;
        if(mask[i]!=0){ p=atomicAdd(&g_M,1); g_mi[p]=i; }
        g_pos[i]=p;
    }
}
__global__ void k_tiefix(){
    int need=g_needed, tc=g_tcnt; if(tc>4096) tc=4096;
    for(int s=0;s<need&&s<tc;s++){
        int mb=s;
        for(int j=s+1;j<tc;j++) if(g_tie[j]<g_tie[mb]) mb=j;
        int tmp=g_tie[s]; g_tie[s]=g_tie[mb]; g_tie[mb]=tmp;
        g_kept[g_tie[s]]=1.0f;
    }
}

// ---------------- pooled degrees ----------------
__global__ void k_sdeg(int n){
    int i=blockIdx.x*blockDim.x+threadIdx.x;
    if(i>=n) return;
    float s=0.0f;
    for(int j=g_off[i];j<g_off[i+1];j++) s+=g_kept[g_eidx[j]];
    g_sdeg[i]=s;
}
__global__ void k_dinvPk(int n){
    int i=blockIdx.x*blockDim.x+threadIdx.x;
    if(i>=n) return;
    float td=0.0f;
    for(int j=g_off[i];j<g_off[i+1];j++) td+=g_sdeg[g_eidx[j]];
    float degP=td+2.0f*g_sdeg[i]+2.0f-(float)g_cc[i];
    g_dinvP[i]=(g_kept[i]>0.5f)?rsqrtf(degP):0.0f;
}

// ------- paired-weight smem loader ------------------------------------------------
__device__ __forceinline__ void load_paired(float* sW, const float* __restrict__ W, int tid){
    for(int i=tid*4;i<256*64;i+=256*4){
        int g=i>>6, f0=i&63;
        int j=g>>5, lg=g&31, kp=j>>1, half=j&1;
        int dbase=kp*64+lg*2+half;
        float4 w=*(const float4*)&W[i];
        sW[dbase+(f0+0)*256]=w.x; sW[dbase+(f0+1)*256]=w.y;
        sW[dbase+(f0+2)*256]=w.z; sW[dbase+(f0+3)*256]=w.w;
    }
}

// ------- Gx precompute ------------------------------------------------------------
__global__ __launch_bounds__(256) void k_gx(const float* __restrict__ Xsrc,
    const float* __restrict__ Wih, const float* __restrict__ bih,
    const float* __restrict__ bhh, int n){
    extern __shared__ float sWi[];
    int tid=threadIdx.x;
    load_paired(sWi,Wih,tid);
    __syncthreads();
    int wid=tid>>5, lane=tid&31;
    unsigned long long bs[4];
    #pragma unroll
    for(int kp=0;kp<4;kp++){
        float blo=bih[lane+64*kp]+bhh[lane+64*kp];
        float bhi=bih[lane+64*kp+32]+bhh[lane+64*kp+32];
        PACK2(bs[kp],blo,bhi);
    }
    unsigned long long* G=g_GX;
    for(int r0=(blockIdx.x*8+wid)*2; r0<n; r0+=gridDim.x*16){
        int r1=r0+1; bool has1=r1<n;
        float xl0=Xsrc[r0*64+lane], xh0=Xsrc[r0*64+lane+32];
        float xl1=has1?Xsrc[r1*64+lane]:0.0f, xh1=has1?Xsrc[r1*64+lane+32]:0.0f;
        unsigned long long a0[4],a1[4];
        #pragma unroll
        for(int kp=0;kp<4;kp++){ a0[kp]=bs[kp]; a1[kp]=bs[kp]; }
        #define GX_F(F,X0,X1S) { \
            const unsigned long long* wp=(const unsigned long long*)&sWi[(F)*256]+lane; \
            unsigned long long w0=wp[0],w1=wp[32],w2=wp[64],w3=wp[96]; \
            float xv0=__shfl_sync(0xffffffffu,X0,(F)&31); \
            float xv1=__shfl_sync(0xffffffffu,X1S,(F)&31); \
            unsigned long long p0,p1; BCAST2(p0,xv0); BCAST2(p1,xv1); \
            FMA2(a0[0],p0,w0); FMA2(a0[1],p0,w1); FMA2(a0[2],p0,w2); FMA2(a0[3],p0,w3); \
            FMA2(a1[0],p1,w0); FMA2(a1[1],p1,w1); FMA2(a1[2],p1,w2); FMA2(a1[3],p1,w3); }
        #pragma unroll 8
        for(int f=0;f<32;f++) GX_F(f,xl0,xl1)
        #pragma unroll 8
        for(int f=32;f<64;f++) GX_F(f,xh0,xh1)
        #undef GX_F
        #pragma unroll
        for(int kp=0;kp<4;kp++){
            G[r0*128+kp*32+lane]=a0[kp];
            if(has1) G[r1*128+kp*32+lane]=a1[kp];
        }
    }
}

// ------- LSTM recurrence (h-part only). DIRECT=1 writes out[rid] rows -------------
template<int DIRECT>
__global__ __launch_bounds__(256) void k_lstm(
    const float* __restrict__ Whh, const float* __restrict__ bih,
    const float* __restrict__ bhh, float* __restrict__ out){
    extern __shared__ float sWh[];
    int tid=threadIdx.x;
    load_paired(sWh,Whh,tid);
    __syncthreads();
    int wid=tid>>5, lane=tid&31;
    int M=g_M;
    unsigned long long bs[4];
    #pragma unroll
    for(int kp=0;kp<4;kp++){
        float blo=bih[lane+64*kp]+bhh[lane+64*kp];
        float bhi=bih[lane+64*kp+32]+bhh[lane+64*kp+32];
        PACK2(bs[kp],blo,bhi);
    }
    const unsigned long long* G=g_GX;
    for(int base=(blockIdx.x*8+wid)*4; base<M; base+=gridDim.x*32){
        int rid[4];
        #pragma unroll
        for(int nn=0;nn<4;nn++) rid[nn]=(base+nn<M)?g_mi[base+nn]:-1;
        float hl[4]={0,0,0,0}, hh[4]={0,0,0,0}, cl[4]={0,0,0,0}, ch[4]={0,0,0,0};
        for(int t=0;t<5;t++){
            unsigned long long acc[4][4];
            #pragma unroll
            for(int nn=0;nn<4;nn++){
                int sr=rid[nn]-4+t;
                bool ok=(rid[nn]>=0)&&(sr>=0);
                const unsigned long long* gp=G+(ok?sr:0)*128+lane;
                #pragma unroll
                for(int kp=0;kp<4;kp++) acc[nn][kp]=ok?gp[kp*32]:bs[kp];
            }
            if(t>0){
                #define LSTM_F(F,HS) { \
                    const unsigned long long* whP=(const unsigned long long*)&sWh[(F)*256]+lane; \
                    unsigned long long w0=whP[0],w1=whP[32],w2=whP[64],w3=whP[96]; \
                    _Pragma("unroll") \
                    for(int nn=0;nn<4;nn++){ \
                        float hv=__shfl_sync(0xffffffffu,HS[nn],(F)&31); \
                        unsigned long long hp; BCAST2(hp,hv); \
                        FMA2(acc[nn][0],hp,w0); FMA2(acc[nn][1],hp,w1); \
                        FMA2(acc[nn][2],hp,w2); FMA2(acc[nn][3],hp,w3); \
                    } }
                #pragma unroll 8
                for(int f=0;f<32;f++) LSTM_F(f,hl)
                #pragma unroll 8
                for(int f=32;f<64;f++) LSTM_F(f,hh)
                #undef LSTM_F
            }
            #pragma unroll
            for(int nn=0;nn<4;nn++){
                float il,ih,fl,fh,gl,gh,ol,oh;
                UNPACK2(il,ih,acc[nn][0]);
                UNPACK2(fl,fh,acc[nn][1]);
                UNPACK2(gl,gh,acc[nn][2]);
                UNPACK2(ol,oh,acc[nn][3]);
                cl[nn]=sigf(fl)*cl[nn]+sigf(il)*tanhf(gl); hl[nn]=sigf(ol)*tanhf(cl[nn]);
                ch[nn]=sigf(fh)*ch[nn]+sigf(ih)*tanhf(gh); hh[nn]=sigf(oh)*tanhf(ch[nn]);
            }
        }
        #pragma unroll
        for(int nn=0;nn<4;nn++){
            if(rid[nn]>=0){
                int orow=DIRECT?rid[nn]:(base+nn);
                out[orow*64+lane]=hl[nn];
                out[orow*64+lane+32]=hh[nn];
            }
        }
    }
}

// ---------------- host ----------------
extern "C" void kernel_launch(void* const* d_in, const int* in_sizes, int n_in,
                              void* d_out, int out_size){
    const float* x=(const float*)d_in[0];
    const int* row=(const int*)d_in[1];
    const int* mask=(const int*)d_in[2];
    const float* W0=(const float*)d_in[3];  const float* b0=(const float*)d_in[4];
    const float* W1=(const float*)d_in[5];  const float* b1=(const float*)d_in[6];
    const float* pw=(const float*)d_in[7];
    const float* Wu=(const float*)d_in[8];  const float* bu=(const float*)d_in[9];
    const float* l0wih=(const float*)d_in[10]; const float* l0whh=(const float*)d_in[11];
    const float* l0bih=(const float*)d_in[12]; const float* l0bhh=(const float*)d_in[13];
    const float* fwih=(const float*)d_in[14];  const float* fwhh=(const float*)d_in[15];
    const float* fbih=(const float*)d_in[16];  const float* fbhh=(const float*)d_in[17];
    float* out=(float*)d_out;

    int n=in_sizes[0]/32;
    int e=in_sizes[1]/2;
    const int* col=row+e;
    int kk=(n+1)/2;
    int GN=(n+255)/256, GE=(e+255)/256;
    int GW=(n*32+255)/256;

    static cudaStream_t sA=0,sB=0;
    static cudaEvent_t evRoot=0,evG=0,evCSR=0,evCC=0,evX1=0,evMik=0,evL0=0;
    if(!sA){
        cudaFuncSetAttribute(k_lstm<0>, cudaFuncAttributeMaxDynamicSharedMemorySize, WSMEM);
        cudaFuncSetAttribute(k_lstm<1>, cudaFuncAttributeMaxDynamicSharedMemorySize, WSMEM);
        cudaFuncSetAttribute(k_gx,      cudaFuncAttributeMaxDynamicSharedMemorySize, WSMEM);
        cudaStreamCreateWithFlags(&sA,cudaStreamNonBlocking);
        cudaStreamCreateWithFlags(&sB,cudaStreamNonBlocking);
        cudaEventCreateWithFlags(&evRoot,cudaEventDisableTiming);
        cudaEventCreateWithFlags(&evG,cudaEventDisableTiming);
        cudaEventCreateWithFlags(&evCSR,cudaEventDisableTiming);
        cudaEventCreateWithFlags(&evCC,cudaEventDisableTiming);
        cudaEventCreateWithFlags(&evX1,cudaEventDisableTiming);
        cudaEventCreateWithFlags(&evMik,cudaEventDisableTiming);
        cudaEventCreateWithFlags(&evL0,cudaEventDisableTiming);
    }

    float *dX1,*dH,*dB1,*dB2,*dS;
    cudaGetSymbolAddress((void**)&dX1,g_X1);
    cudaGetSymbolAddress((void**)&dH,g_H);
    cudaGetSymbolAddress((void**)&dB1,g_B1);
    cudaGetSymbolAddress((void**)&dB2,g_B2);
    cudaGetSymbolAddress((void**)&dS,g_S);
    float *dscore; cudaGetSymbolAddress((void**)&dscore,g_score);
    float *ddinvP; cudaGetSymbolAddress((void**)&ddinvP,g_dinvP);
    float *ddinv0; cudaGetSymbolAddress((void**)&ddinv0,g_dinv0);

    // fork: conv0 GEMM on sA (depends on nothing)
    cudaEventRecord(evRoot,0);
    cudaStreamWaitEvent(sA,evRoot,0);
    k_gemm<32,0><<<(n+15)/16,256,0,sA>>>(x,W0,(const float*)0,dH,(const float*)0,(float*)0,(const float*)0,(const float*)0,(const float*)0,n);
    cudaEventRecord(evG,sA);

    // main: init + indeg + CSR build (no hash)
    k_init<<<256,256>>>(pw,n);
    k_indeg<<<GE,256>>>(col,e);
    k_scan1<<<GN,256>>>(n);
    k_scan2<<<1,256>>>(GN);
    k_scan3<<<GN,256>>>(n,e);
    k_place<<<GE,256>>>(row,col,e);
    cudaEventRecord(evCSR,0);

    // cc via CSR-count on sB (hidden under conv0 gather + selection)
    cudaStreamWaitEvent(sB,evCSR,0);
    k_cc<<<GE,256,0,sB>>>(row,col,e);
    cudaEventRecord(evCC,sB);

    // conv0 gather (needs H from sA + CSR)
    cudaStreamWaitEvent(0,evG,0);
    k_gcng<1><<<GW,256>>>(dH,b0,pw,dX1,n);
    cudaEventRecord(evX1,0);

    // LSTM0 Gx on sB (needs only X1; queued after cc on sB)
    cudaStreamWaitEvent(sB,evX1,0);
    k_gx<<<PGRID,256,WSMEM,sB>>>(dX1,l0wih,l0bih,l0bhh,n);

    // selection on main
    k_find1<<<1,256>>>(kk);
    k_hist2k<<<GN,256>>>(n);
    k_find2<<<1,256>>>(kk);
    k_markmik<<<GN,256>>>(mask,n);
    cudaEventRecord(evMik,0);
    k_tiefix<<<1,1>>>();

    // LSTM0 recurrence on sB (needs g_mi/g_M)
    cudaStreamWaitEvent(sB,evMik,0);
    k_lstm<0><<<PGRID,256,WSMEM,sB>>>(l0whh,l0bih,l0bhh,dB1);   // h0 -> B1 compact
    cudaEventRecord(evL0,sB);

    // branch A on main: pooled degrees + conv1
    k_sdeg<<<GN,256>>>(n);
    cudaStreamWaitEvent(0,evCC,0);
    k_dinvPk<<<GN,256>>>(n);
    k_gemm<64,0><<<(n+15)/16,256>>>(dX1,W1,dscore,dH,(const float*)0,dB2,ddinvP,(const float*)0,(const float*)0,n); // h2->H, m->B2
    k_sg<<<GW,256>>>(dB2,dS,n);
    k_tup<<<GW,256>>>(dS,dH,b1,dB2,n);                          // up -> B2

    // join LSTM0; Wu GEMM with inline RES; final gather; final LSTM
    cudaStreamWaitEvent(0,evL0,0);
    k_gemm<64,1><<<(n+15)/16,256>>>(dX1,Wu,(const float*)0,dH,ddinv0,(float*)0,(const float*)0,dB1,dB2,n);
    k_gcng<0><<<GW,256>>>(dH,bu,(const float*)0,out,n);
    k_gx<<<PGRID,256,WSMEM>>>(out,fwih,fbih,fbhh,n);
    k_lstm<1><<<PGRID,256,WSMEM>>>(fwhh,fbih,fbhh,out);
}

// round 15
// speedup vs baseline: 1.5131x; 1.0571x over previous
#include <cuda_runtime.h>
#include <math.h>

#define NMAX 50000
#define EMAX 400000
#define WSMEM (64*256*4)
#define PGRID 444

// ---------------- scratch ----------------
__device__ float g_X1 [NMAX*64];
__device__ float g_H  [NMAX*64];
__device__ float g_B1 [NMAX*64];
__device__ float g_B2 [NMAX*64];
__device__ float g_S  [NMAX*64];
__device__ unsigned long long g_GX[NMAX*128];
__device__ float g_dinv0[NMAX];
__device__ float g_dinvP[NMAX];
__device__ float g_score[NMAX];
__device__ float g_kept[NMAX];
__device__ float g_sdeg[NMAX];
__device__ unsigned g_key[NMAX];
__device__ int   g_icnt[NMAX];
__device__ int   g_cc[NMAX];
__device__ int   g_mi[NMAX];
__device__ int   g_pos[NMAX];
__device__ int   g_off[NMAX+1];
__device__ int   g_cur[NMAX];
__device__ int   g_eidx[EMAX];
__device__ int   g_bsum[256];
__device__ int   g_bscan[256];
__device__ int   g_hist[65536];
__device__ int   g_hist2[65536];
__device__ int   g_tie[4096];
__device__ int   g_M, g_tcnt, g_selB, g_before, g_needed;
__device__ unsigned g_T;
__device__ float g_pwnorm;

__device__ __forceinline__ float sigf(float x){ return 1.0f/(1.0f+expf(-x)); }

#define FMA2(A,B,C) asm("fma.rn.f32x2 %0,%1,%2,%0;":"+l"(A):"l"(B),"l"(C))
#define PACK2(D,LO,HI) asm("mov.b64 %0,{%1,%2};":"=l"(D):"f"(LO),"f"(HI))
#define BCAST2(D,V) asm("mov.b64 %0,{%1,%1};":"=l"(D):"f"(V))
#define UNPACK2(LO,HI,S) asm("mov.b64 {%0,%1},%2;":"=f"(LO),"=f"(HI):"l"(S))

// ------- fused init ----------------------------------------------------------------
__global__ void k_init(const float* __restrict__ pw, int n){
    int i=blockIdx.x*blockDim.x+threadIdx.x;
    if(i<n){ g_icnt[i]=0; g_cc[i]=0; }
    if(i<65536){ g_hist[i]=0; g_hist2[i]=0; }
    if(i==0){ g_M=0; g_tcnt=0; }
    if(blockIdx.x==0&&threadIdx.x<32){
        int l=threadIdx.x;
        float v=pw[l]*pw[l]+pw[l+32]*pw[l+32];
        for(int o=16;o;o>>=1) v+=__shfl_down_sync(0xffffffffu,v,o);
        if(l==0) g_pwnorm=sqrtf(v);
    }
}

// ------- early mask compaction ------------------------------------------------------
__global__ void k_mik(const int* __restrict__ mask, int n){
    int i=blockIdx.x*blockDim.x+threadIdx.x;
    if(i<n){
        int p=-1;
        if(mask[i]!=0){ p=atomicAdd(&g_M,1); g_mi[p]=i; }
        g_pos[i]=p;
    }
}

// ------- edge pass: in-degree ------------------------------------------------------
__global__ void k_indeg(const int* __restrict__ col, int e){
    int i=blockIdx.x*blockDim.x+threadIdx.x;
    if(i<e) atomicAdd(&g_icnt[col[i]],1);
}

// ------- CSR build ------------------------------------------------------------------
__global__ void k_scan1(int n){
    __shared__ int s[256];
    int t=threadIdx.x, i=blockIdx.x*256+t;
    int v=(i<n)?g_icnt[i]:0;
    if(i<n) g_dinv0[i]=rsqrtf((float)v+2.0f);
    s[t]=v; __syncthreads();
    for(int o=128;o;o>>=1){ if(t<o) s[t]+=s[t+o]; __syncthreads(); }
    if(t==0) g_bsum[blockIdx.x]=s[0];
}
__global__ void k_scan2(int nb){
    __shared__ int s[256];
    int t=threadIdx.x;
    int v=(t<nb)?g_bsum[t]:0;
    s[t]=v; __syncthreads();
    for(int o=1;o<256;o<<=1){
        int u=(t>=o)?s[t-o]:0; __syncthreads();
        s[t]+=u; __syncthreads();
    }
    g_bscan[t]=s[t]-v;
}
__global__ void k_scan3(int n, int e){
    __shared__ int s[256];
    int t=threadIdx.x, i=blockIdx.x*256+t;
    int v=(i<n)?g_icnt[i]:0;
    s[t]=v; __syncthreads();
    for(int o=1;o<256;o<<=1){
        int u=(t>=o)?s[t-o]:0; __syncthreads();
        s[t]+=u; __syncthreads();
    }
    if(i<n){
        int off=g_bscan[blockIdx.x]+s[t]-v;
        g_off[i]=off; g_cur[i]=off;
        if(i==n-1) g_off[n]=e;
    }
}
__global__ void k_place(const int* __restrict__ row, const int* __restrict__ col, int e){
    int i=blockIdx.x*blockDim.x+threadIdx.x;
    if(i<e){
        int p=atomicAdd(&g_cur[col[i]],1);
        g_eidx[p]=row[i];
    }
}
__global__ void k_cc(const int* __restrict__ row, const int* __restrict__ col, int e){
    int i=blockIdx.x*blockDim.x+threadIdx.x;
    if(i>=e) return;
    int r=row[i], c=col[i];
    int s0=g_off[r], s1=g_off[r+1];
    int cnt=0;
    for(int j=s0;j<s1;j++) cnt+=(g_eidx[j]==c);
    if(cnt) atomicAdd(&g_cc[r],cnt);
}

// ------- dense GEMM (XIN=1: input row = (pos>=0?alt[pos]:X[row]) + add[row]) -------
template<int K,int XIN>
__global__ void k_gemm(const float* __restrict__ X, const float* __restrict__ W,
                       const float* __restrict__ rs, float* __restrict__ out,
                       const float* __restrict__ alt, const float* __restrict__ add, int n){
    __shared__ float sW[K*64];
    __shared__ float sX[16*K];
    int tid=threadIdx.x;
    for(int i=tid;i<K*64;i+=256) sW[i]=W[i];
    int r0=blockIdx.x*16;
    for(int i=tid;i<16*K;i+=256){
        int rr=i/K, kk=i%K, row=r0+rr;
        float v=0.0f;
        if(row<n){
            if(XIN){
                int p=g_pos[row];
                v=((p>=0)?alt[p*64+kk]:X[row*64+kk])+add[row*64+kk];
            }else{
                v=X[row*K+kk]; if(rs) v*=rs[row];
            }
        }
        sX[i]=v;
    }
    __syncthreads();
    int c=tid&63, rg=tid>>6;
    float a0=0,a1=0,a2=0,a3=0;
    #pragma unroll 8
    for(int kk=0;kk<K;kk++){
        float w=sW[kk*64+c];
        a0+=sX[(rg*4+0)*K+kk]*w;
        a1+=sX[(rg*4+1)*K+kk]*w;
        a2+=sX[(rg*4+2)*K+kk]*w;
        a3+=sX[(rg*4+3)*K+kk]*w;
    }
    int row=r0+rg*4;
    #pragma unroll
    for(int rr=0;rr<4;rr++){
        float a=(rr==0)?a0:(rr==1)?a1:(rr==2)?a2:a3;
        if(row+rr<n) out[(row+rr)*64+c]=a;
    }
}

// ------- GCN gather (warp/node), per-edge dinv0 scaling in BOTH modes --------------
// out[c] = dinv0[c]*( Σ_in dinv0[r]*H[r] + 2*dinv0[c]*H[c] ) + b ;  MODE 1 adds relu+score
template<int MODE>
__global__ void k_gcng(const float* __restrict__ Hs, const float* __restrict__ b,
                       const float* __restrict__ pw, float* __restrict__ out, int n){
    int node=(blockIdx.x*blockDim.x+threadIdx.x)>>5;
    int l=threadIdx.x&31;
    if(node>=n) return;
    float d=g_dinv0[node];
    float alo=2.0f*d*Hs[node*64+l], ahi=2.0f*d*Hs[node*64+l+32];
    int s0=g_off[node], s1=g_off[node+1];
    for(int j=s0;j<s1;j++){
        int r=g_eidx[j];
        float dr=g_dinv0[r];
        alo+=dr*Hs[r*64+l];
        ahi+=dr*Hs[r*64+l+32];
    }
    float vlo=d*alo+b[l], vhi=d*ahi+b[l+32];
    if(MODE==1){
        vlo=fmaxf(vlo,0.0f); vhi=fmaxf(vhi,0.0f);
        out[node*64+l]=vlo; out[node*64+l+32]=vhi;
        float s=vlo*pw[l]+vhi*pw[l+32];
        for(int o=16;o;o>>=1) s+=__shfl_down_sync(0xffffffffu,s,o);
        if(l==0){
            float sc=tanhf(s/g_pwnorm);
            g_score[node]=sc;
            unsigned bb=__float_as_uint(sc);
            unsigned key=(bb&0x80000000u)?~bb:(bb|0x80000000u);
            g_key[node]=key;
            atomicAdd(&g_hist[key>>16],1);
        }
    }else{
        out[node*64+l]=vlo; out[node*64+l+32]=vhi;
    }
}
// s[c] = Σ_in dinvP[r]*h2[r]
__global__ void k_sg(const float* __restrict__ h2, float* __restrict__ s, int n){
    int node=(blockIdx.x*blockDim.x+threadIdx.x)>>5;
    int l=threadIdx.x&31;
    if(node>=n) return;
    float alo=0.0f, ahi=0.0f;
    int s0=g_off[node], s1=g_off[node+1];
    for(int j=s0;j<s1;j++){
        int r=g_eidx[j];
        float dr=g_dinvP[r];
        if(dr!=0.0f){
            alo+=dr*h2[r*64+l];
            ahi+=dr*h2[r*64+l+32];
        }
    }
    s[node*64+l]=alo; s[node*64+l+32]=ahi;
}
// up = relu(dp*(Σ_in s[r] + 2*s[node] + (2-cc)*dp*h2[node]) + b1)
__global__ void k_tup(const float* __restrict__ s, const float* __restrict__ h2,
                      const float* __restrict__ b1, float* __restrict__ up, int n){
    int node=(blockIdx.x*blockDim.x+threadIdx.x)>>5;
    int l=threadIdx.x&31;
    if(node>=n) return;
    float dp=g_dinvP[node];
    if(dp==0.0f){
        up[node*64+l]=0.0f; up[node*64+l+32]=0.0f;
        return;
    }
    float alo=0.0f, ahi=0.0f;
    int s0=g_off[node], s1=g_off[node+1];
    for(int j=s0;j<s1;j++){
        int r=g_eidx[j];
        alo+=s[r*64+l];
        ahi+=s[r*64+l+32];
    }
    float cf=(2.0f-(float)g_cc[node])*dp;   // inner cf*h2, outer dp → (2-cc)*dp^2*h2 = (2-cc)*dp*m
    float vlo=fmaxf(dp*(alo+2.0f*s[node*64+l]   +cf*h2[node*64+l])   +b1[l],   0.0f);
    float vhi=fmaxf(dp*(ahi+2.0f*s[node*64+l+32]+cf*h2[node*64+l+32])+b1[l+32],0.0f);
    up[node*64+l]=vlo; up[node*64+l+32]=vhi;
}

// ---------------- radix select ----------------
__global__ void k_find1(int kk){
    __shared__ int cs[256]; __shared__ int fine[256]; __shared__ int sel;
    int t=threadIdx.x, s=0;
    for(int b=0;b<256;b++) s+=g_hist[t*256+b];
    cs[t]=s; __syncthreads();
    if(t==0){
        int acc=0, c;
        for(c=255;c>0;c--){ if(acc+cs[c]>=kk) break; acc+=cs[c]; }
        sel=c; g_before=acc;
    }
    __syncthreads();
    int c=sel;
    fine[t]=g_hist[c*256+t];
    __syncthreads();
    if(t==0){
        int acc=g_before;
        for(int b=255;b>=0;b--){
            acc+=fine[b];
            if(acc>=kk){ g_selB=c*256+b; g_before=acc-fine[b]; return; }
        }
        g_selB=c*256;
    }
}
__global__ void k_hist2k(int n){
    int i=blockIdx.x*blockDim.x+threadIdx.x;
    if(i<n){ unsigned u=g_key[i]; if((int)(u>>16)==g_selB) atomicAdd(&g_hist2[u&0xFFFFu],1); }
}
__global__ void k_find2(int kk){
    __shared__ int cs[256]; __shared__ int fine[256]; __shared__ int sel;
    int t=threadIdx.x, s=0;
    for(int b=0;b<256;b++) s+=g_hist2[t*256+b];
    cs[t]=s; __syncthreads();
    int rem=kk-g_before;
    if(t==0){
        int acc=0, c;
        for(c=255;c>0;c--){ if(acc+cs[c]>=rem) break; acc+=cs[c]; }
        sel=c; g_needed=acc;
    }
    __syncthreads();
    int c=sel;
    fine[t]=g_hist2[c*256+t];
    __syncthreads();
    if(t==0){
        int acc=g_needed;
        for(int b=255;b>=0;b--){
            acc+=fine[b];
            if(acc>=rem){
                g_T=((unsigned)g_selB<<16)|(unsigned)(c*256+b);
                g_needed=rem-(acc-fine[b]);
                return;
            }
        }
        g_T=(unsigned)g_selB<<16; g_needed=0;
    }
}
__global__ void k_markkept(int n){
    int i=blockIdx.x*blockDim.x+threadIdx.x;
    if(i<n){
        unsigned u=g_key[i];
        g_kept[i]=(u>g_T)?1.0f:0.0f;
        if(u==g_T){ int p=atomicAdd(&g_tcnt,1); if(p<4096) g_tie[p]=i; }
    }
}
__global__ void k_tiefix(){
    int need=g_needed, tc=g_tcnt; if(tc>4096) tc=4096;
    for(int s=0;s<need&&s<tc;s++){
        int mb=s;
        for(int j=s+1;j<tc;j++) if(g_tie[j]<g_tie[mb]) mb=j;
        int tmp=g_tie[s]; g_tie[s]=g_tie[mb]; g_tie[mb]=tmp;
        g_kept[g_tie[s]]=1.0f;
    }
}

// ---------------- pooled degrees ----------------
__global__ void k_sdeg(int n){
    int i=blockIdx.x*blockDim.x+threadIdx.x;
    if(i>=n) return;
    float s=0.0f;
    for(int j=g_off[i];j<g_off[i+1];j++) s+=g_kept[g_eidx[j]];
    g_sdeg[i]=s;
}
__global__ void k_dinvPk(int n){
    int i=blockIdx.x*blockDim.x+threadIdx.x;
    if(i>=n) return;
    float td=0.0f;
    for(int j=g_off[i];j<g_off[i+1];j++) td+=g_sdeg[g_eidx[j]];
    float degP=td+2.0f*g_sdeg[i]+2.0f-(float)g_cc[i];
    g_dinvP[i]=(g_kept[i]>0.5f)?rsqrtf(degP):0.0f;
}

// ------- paired-weight smem loader ------------------------------------------------
__device__ __forceinline__ void load_paired(float* sW, const float* __restrict__ W, int tid){
    for(int i=tid*4;i<256*64;i+=256*4){
        int g=i>>6, f0=i&63;
        int j=g>>5, lg=g&31, kp=j>>1, half=j&1;
        int dbase=kp*64+lg*2+half;
        float4 w=*(const float4*)&W[i];
        sW[dbase+(f0+0)*256]=w.x; sW[dbase+(f0+1)*256]=w.y;
        sW[dbase+(f0+2)*256]=w.z; sW[dbase+(f0+3)*256]=w.w;
    }
}

// ------- Gx precompute ------------------------------------------------------------
__global__ __launch_bounds__(256) void k_gx(const float* __restrict__ Xsrc,
    const float* __restrict__ Wih, const float* __restrict__ bih,
    const float* __restrict__ bhh, int n){
    extern __shared__ float sWi[];
    int tid=threadIdx.x;
    load_paired(sWi,Wih,tid);
    __syncthreads();
    int wid=tid>>5, lane=tid&31;
    unsigned long long bs[4];
    #pragma unroll
    for(int kp=0;kp<4;kp++){
        float blo=bih[lane+64*kp]+bhh[lane+64*kp];
        float bhi=bih[lane+64*kp+32]+bhh[lane+64*kp+32];
        PACK2(bs[kp],blo,bhi);
    }
    unsigned long long* G=g_GX;
    for(int r0=(blockIdx.x*8+wid)*2; r0<n; r0+=gridDim.x*16){
        int r1=r0+1; bool has1=r1<n;
        float xl0=Xsrc[r0*64+lane], xh0=Xsrc[r0*64+lane+32];
        float xl1=has1?Xsrc[r1*64+lane]:0.0f, xh1=has1?Xsrc[r1*64+lane+32]:0.0f;
        unsigned long long a0[4],a1[4];
        #pragma unroll
        for(int kp=0;kp<4;kp++){ a0[kp]=bs[kp]; a1[kp]=bs[kp]; }
        #define GX_F(F,X0,X1S) { \
            const unsigned long long* wp=(const unsigned long long*)&sWi[(F)*256]+lane; \
            unsigned long long w0=wp[0],w1=wp[32],w2=wp[64],w3=wp[96]; \
            float xv0=__shfl_sync(0xffffffffu,X0,(F)&31); \
            float xv1=__shfl_sync(0xffffffffu,X1S,(F)&31); \
            unsigned long long p0,p1; BCAST2(p0,xv0); BCAST2(p1,xv1); \
            FMA2(a0[0],p0,w0); FMA2(a0[1],p0,w1); FMA2(a0[2],p0,w2); FMA2(a0[3],p0,w3); \
            FMA2(a1[0],p1,w0); FMA2(a1[1],p1,w1); FMA2(a1[2],p1,w2); FMA2(a1[3],p1,w3); }
        #pragma unroll 8
        for(int f=0;f<32;f++) GX_F(f,xl0,xl1)
        #pragma unroll 8
        for(int f=32;f<64;f++) GX_F(f,xh0,xh1)
        #undef GX_F
        #pragma unroll
        for(int kp=0;kp<4;kp++){
            G[r0*128+kp*32+lane]=a0[kp];
            if(has1) G[r1*128+kp*32+lane]=a1[kp];
        }
    }
}

// ------- LSTM recurrence (h-part only). DIRECT=1 writes out[rid] rows -------------
template<int DIRECT>
__global__ __launch_bounds__(256) void k_lstm(
    const float* __restrict__ Whh, const float* __restrict__ bih,
    const float* __restrict__ bhh, float* __restrict__ out){
    extern __shared__ float sWh[];
    int tid=threadIdx.x;
    load_paired(sWh,Whh,tid);
    __syncthreads();
    int wid=tid>>5, lane=tid&31;
    int M=g_M;
    unsigned long long bs[4];
    #pragma unroll
    for(int kp=0;kp<4;kp++){
        float blo=bih[lane+64*kp]+bhh[lane+64*kp];
        float bhi=bih[lane+64*kp+32]+bhh[lane+64*kp+32];
        PACK2(bs[kp],blo,bhi);
    }
    const unsigned long long* G=g_GX;
    for(int base=(blockIdx.x*8+wid)*4; base<M; base+=gridDim.x*32){
        int rid[4];
        #pragma unroll
        for(int nn=0;nn<4;nn++) rid[nn]=(base+nn<M)?g_mi[base+nn]:-1;
        float hl[4]={0,0,0,0}, hh[4]={0,0,0,0}, cl[4]={0,0,0,0}, ch[4]={0,0,0,0};
        for(int t=0;t<5;t++){
            unsigned long long acc[4][4];
            #pragma unroll
            for(int nn=0;nn<4;nn++){
                int sr=rid[nn]-4+t;
                bool ok=(rid[nn]>=0)&&(sr>=0);
                const unsigned long long* gp=G+(ok?sr:0)*128+lane;
                #pragma unroll
                for(int kp=0;kp<4;kp++) acc[nn][kp]=ok?gp[kp*32]:bs[kp];
            }
            if(t>0){
                #define LSTM_F(F,HS) { \
                    const unsigned long long* whP=(const unsigned long long*)&sWh[(F)*256]+lane; \
                    unsigned long long w0=whP[0],w1=whP[32],w2=whP[64],w3=whP[96]; \
                    _Pragma("unroll") \
                    for(int nn=0;nn<4;nn++){ \
                        float hv=__shfl_sync(0xffffffffu,HS[nn],(F)&31); \
                        unsigned long long hp; BCAST2(hp,hv); \
                        FMA2(acc[nn][0],hp,w0); FMA2(acc[nn][1],hp,w1); \
                        FMA2(acc[nn][2],hp,w2); FMA2(acc[nn][3],hp,w3); \
                    } }
                #pragma unroll 8
                for(int f=0;f<32;f++) LSTM_F(f,hl)
                #pragma unroll 8
                for(int f=32;f<64;f++) LSTM_F(f,hh)
                #undef LSTM_F
            }
            #pragma unroll
            for(int nn=0;nn<4;nn++){
                float il,ih,fl,fh,gl,gh,ol,oh;
                UNPACK2(il,ih,acc[nn][0]);
                UNPACK2(fl,fh,acc[nn][1]);
                UNPACK2(gl,gh,acc[nn][2]);
                UNPACK2(ol,oh,acc[nn][3]);
                cl[nn]=sigf(fl)*cl[nn]+sigf(il)*tanhf(gl); hl[nn]=sigf(ol)*tanhf(cl[nn]);
                ch[nn]=sigf(fh)*ch[nn]+sigf(ih)*tanhf(gh); hh[nn]=sigf(oh)*tanhf(ch[nn]);
            }
        }
        #pragma unroll
        for(int nn=0;nn<4;nn++){
            if(rid[nn]>=0){
                int orow=DIRECT?rid[nn]:(base+nn);
                out[orow*64+lane]=hl[nn];
                out[orow*64+lane+32]=hh[nn];
            }
        }
    }
}

// ---------------- host ----------------
extern "C" void kernel_launch(void* const* d_in, const int* in_sizes, int n_in,
                              void* d_out, int out_size){
    const float* x=(const float*)d_in[0];
    const int* row=(const int*)d_in[1];
    const int* mask=(const int*)d_in[2];
    const float* W0=(const float*)d_in[3];  const float* b0=(const float*)d_in[4];
    const float* W1=(const float*)d_in[5];  const float* b1=(const float*)d_in[6];
    const float* pw=(const float*)d_in[7];
    const float* Wu=(const float*)d_in[8];  const float* bu=(const float*)d_in[9];
    const float* l0wih=(const float*)d_in[10]; const float* l0whh=(const float*)d_in[11];
    const float* l0bih=(const float*)d_in[12]; const float* l0bhh=(const float*)d_in[13];
    const float* fwih=(const float*)d_in[14];  const float* fwhh=(const float*)d_in[15];
    const float* fbih=(const float*)d_in[16];  const float* fbhh=(const float*)d_in[17];
    float* out=(float*)d_out;

    int n=in_sizes[0]/32;
    int e=in_sizes[1]/2;
    const int* col=row+e;
    int kk=(n+1)/2;
    int GN=(n+255)/256, GE=(e+255)/256;
    int GW=(n*32+255)/256;

    static cudaStream_t sA=0,sB=0,sC=0;
    static cudaEvent_t evRoot=0,evG=0,evInit=0,evMikC=0,evCSR=0,evCC=0,evX1=0,evH2=0,evL0=0;
    if(!sA){
        cudaFuncSetAttribute(k_lstm<0>, cudaFuncAttributeMaxDynamicSharedMemorySize, WSMEM);
        cudaFuncSetAttribute(k_lstm<1>, cudaFuncAttributeMaxDynamicSharedMemorySize, WSMEM);
        cudaFuncSetAttribute(k_gx,      cudaFuncAttributeMaxDynamicSharedMemorySize, WSMEM);
        cudaStreamCreateWithFlags(&sA,cudaStreamNonBlocking);
        cudaStreamCreateWithFlags(&sB,cudaStreamNonBlocking);
        cudaStreamCreateWithFlags(&sC,cudaStreamNonBlocking);
        cudaEventCreateWithFlags(&evRoot,cudaEventDisableTiming);
        cudaEventCreateWithFlags(&evG,cudaEventDisableTiming);
        cudaEventCreateWithFlags(&evInit,cudaEventDisableTiming);
        cudaEventCreateWithFlags(&evMikC,cudaEventDisableTiming);
        cudaEventCreateWithFlags(&evCSR,cudaEventDisableTiming);
        cudaEventCreateWithFlags(&evCC,cudaEventDisableTiming);
        cudaEventCreateWithFlags(&evX1,cudaEventDisableTiming);
        cudaEventCreateWithFlags(&evH2,cudaEventDisableTiming);
        cudaEventCreateWithFlags(&evL0,cudaEventDisableTiming);
    }

    float *dX1,*dH,*dB1,*dB2,*dS;
    cudaGetSymbolAddress((void**)&dX1,g_X1);
    cudaGetSymbolAddress((void**)&dH,g_H);
    cudaGetSymbolAddress((void**)&dB1,g_B1);
    cudaGetSymbolAddress((void**)&dB2,g_B2);
    cudaGetSymbolAddress((void**)&dS,g_S);
    float *dscore; cudaGetSymbolAddress((void**)&dscore,g_score);

    // fork: conv0 GEMM on sA (depends on nothing)
    cudaEventRecord(evRoot,0);
    cudaStreamWaitEvent(sA,evRoot,0);
    k_gemm<32,0><<<(n+15)/16,256,0,sA>>>(x,W0,(const float*)0,dH,(const float*)0,(const float*)0,n);
    cudaEventRecord(evG,sA);

    // main: init
    k_init<<<256,256>>>(pw,n);
    cudaEventRecord(evInit,0);

    // early mask compaction on sC (needs only init + mask)
    cudaStreamWaitEvent(sC,evInit,0);
    k_mik<<<GN,256,0,sC>>>(mask,n);
    cudaEventRecord(evMikC,sC);

    // main: indeg + CSR build
    k_indeg<<<GE,256>>>(col,e);
    k_scan1<<<GN,256>>>(n);
    k_scan2<<<1,256>>>(GN);
    k_scan3<<<GN,256>>>(n,e);
    k_place<<<GE,256>>>(row,col,e);
    cudaEventRecord(evCSR,0);

    // cc via CSR-count on sB
    cudaStreamWaitEvent(sB,evCSR,0);
    k_cc<<<GE,256,0,sB>>>(row,col,e);
    cudaEventRecord(evCC,sB);

    // conv0 gather (needs H from sA + CSR)
    cudaStreamWaitEvent(0,evG,0);
    k_gcng<1><<<GW,256>>>(dH,b0,pw,dX1,n);
    cudaEventRecord(evX1,0);

    // LSTM0 Gx on sB (needs X1), then lstm0 as soon as mi ready (evMikC)
    cudaStreamWaitEvent(sB,evX1,0);
    k_gx<<<PGRID,256,WSMEM,sB>>>(dX1,l0wih,l0bih,l0bhh,n);
    cudaStreamWaitEvent(sB,evMikC,0);
    k_lstm<0><<<PGRID,256,WSMEM,sB>>>(l0whh,l0bih,l0bhh,dB1);   // h0 -> B1 compact
    cudaEventRecord(evL0,sB);

    // h2 GEMM on sA (needs X1 + score)
    cudaStreamWaitEvent(sA,evX1,0);
    k_gemm<64,0><<<(n+15)/16,256,0,sA>>>(dX1,W1,dscore,dH,(const float*)0,(const float*)0,n);
    cudaEventRecord(evH2,sA);

    // selection on main
    k_find1<<<1,256>>>(kk);
    k_hist2k<<<GN,256>>>(n);
    k_find2<<<1,256>>>(kk);
    k_markkept<<<GN,256>>>(n);
    k_tiefix<<<1,1>>>();

    // branch A on main: pooled degrees + s/t gathers
    k_sdeg<<<GN,256>>>(n);
    cudaStreamWaitEvent(0,evCC,0);
    k_dinvPk<<<GN,256>>>(n);
    cudaStreamWaitEvent(0,evH2,0);
    k_sg<<<GW,256>>>(dH,dS,n);                                  // s = Σ dinvP[r]*h2[r]
    k_tup<<<GW,256>>>(dS,dH,b1,dB2,n);                          // up -> B2

    // join LSTM0; Wu GEMM with inline RES; final gather; final LSTM
    cudaStreamWaitEvent(0,evL0,0);
    k_gemm<64,1><<<(n+15)/16,256>>>(dX1,Wu,(const float*)0,dH,dB1,dB2,n);
    k_gcng<0><<<GW,256>>>(dH,bu,(const float*)0,out,n);
    k_gx<<<PGRID,256,WSMEM>>>(out,fwih,fbih,fbhh,n);
    k_lstm<1><<<PGRID,256,WSMEM>>>(fwhh,fbih,fbhh,out);
}